// round 7
// baseline (speedup 1.0000x reference)
#include <cuda_runtime.h>
#include <cuda_fp16.h>
#include <math.h>
#include <stdint.h>

#define N_NODES 131072
#define N_DST   16384
#define DEG     16
#define N_EDGES (N_DST*DEG)
#define HID     256

// ---------------- global scratch (device globals: no runtime alloc) --------
__device__ __align__(16) __half g_h1 [(size_t)N_NODES * 256];
__device__ __align__(16) __half g_h2a[(size_t)N_NODES * 256];
__device__ __align__(16) __half g_hh [(size_t)N_NODES * 256];
__device__ __align__(16) __half g_eaH[(size_t)N_NODES * 512];
__device__ __align__(16) float  g_eb [(size_t)N_DST   * 512];
__device__ __align__(16) __half g_w2h [256*256];
__device__ __align__(16) __half g_w3h [256*256];
__device__ __align__(16) __half g_mw1h[512*512];
__device__ __align__(16) __half g_mw2h[256*512];
__device__ __align__(16) __half g_mw3h[256*256];
__device__ int g_is64;

__device__ __forceinline__ float gelu_exact(float x){
    return 0.5f * x * (1.0f + erff(x * 0.70710678118654752f));
}
__device__ __forceinline__ uint32_t smem_u32(const void* p){
    uint32_t a;
    asm("{ .reg .u64 t; cvta.to.shared.u64 t, %1; cvt.u32.u64 %0, t; }" : "=r"(a) : "l"(p));
    return a;
}
__device__ __forceinline__ void mma16(float* c, const uint32_t* a, const uint32_t* b){
    asm volatile("mma.sync.aligned.m16n8k16.row.col.f32.f16.f16.f32 "
        "{%0,%1,%2,%3}, {%4,%5,%6,%7}, {%8,%9}, {%0,%1,%2,%3};"
        : "+f"(c[0]), "+f"(c[1]), "+f"(c[2]), "+f"(c[3])
        : "r"(a[0]), "r"(a[1]), "r"(a[2]), "r"(a[3]), "r"(b[0]), "r"(b[1]));
}
__device__ __forceinline__ void ldsm4(uint32_t& r0, uint32_t& r1, uint32_t& r2, uint32_t& r3,
                                      uint32_t addr){
    asm volatile("ldmatrix.sync.aligned.m8n8.x4.shared.b16 {%0,%1,%2,%3}, [%4];"
        : "=r"(r0), "=r"(r1), "=r"(r2), "=r"(r3) : "r"(addr));
}
#define CP16(dst, src) \
    asm volatile("cp.async.ca.shared.global [%0], [%1], 16;" :: "r"(dst), "l"(src) : "memory")
#define CP_COMMIT() asm volatile("cp.async.commit_group;" ::: "memory")
#define CP_WAIT2()  asm volatile("cp.async.wait_group 2;"  ::: "memory")
#define CP_WAIT1()  asm volatile("cp.async.wait_group 1;"  ::: "memory")

// ---------------------------------------------------------------------------
__global__ void detect_kernel(const int* __restrict__ me32){
    if (threadIdx.x == 0 && blockIdx.x == 0) g_is64 = (me32[32] != 1) ? 1 : 0;
}

// one-shot fp16 conversion of all five weight matrices (float4 granularity)
__global__ __launch_bounds__(256)
void f2h_all(const float* __restrict__ w2, const float* __restrict__ w3,
             const float* __restrict__ m1, const float* __restrict__ m2,
             const float* __restrict__ m3,
             __half* __restrict__ dw2, __half* __restrict__ dw3,
             __half* __restrict__ dm1, __half* __restrict__ dm2,
             __half* __restrict__ dm3)
{
    int i = blockIdx.x*256 + threadIdx.x;          // float4 index, total 147456
    const float* s; __half* d; int off;
    if      (i <  16384){ s = w2; d = dw2; off = i; }
    else if (i <  32768){ s = w3; d = dw3; off = i - 16384; }
    else if (i <  98304){ s = m1; d = dm1; off = i - 32768; }
    else if (i < 131072){ s = m2; d = dm2; off = i - 98304; }
    else                { s = m3; d = dm3; off = i - 131072; }
    float4 v = ((const float4*)s)[off];
    __half2 h0 = __floats2half2_rn(v.x, v.y), h1 = __floats2half2_rn(v.z, v.w);
    uint2 pk;
    pk.x = *reinterpret_cast<uint32_t*>(&h0);
    pk.y = *reinterpret_cast<uint32_t*>(&h1);
    ((uint2*)d)[off] = pk;
}

// h1 = gelu(x @ W1^T + b1), K=3: fp32 math, fp16 store.
__global__ __launch_bounds__(256)
void h1_kernel(const float* __restrict__ x,
               const float* __restrict__ w1, const float* __restrict__ b1){
    __shared__ float sx[64*3];
    const int t  = threadIdx.x;
    const int n0 = blockIdx.x * 64;
    for (int i = t; i < 64*3; i += 256) sx[i] = x[(size_t)n0*3 + i];
    __syncthreads();
    const float wa = w1[t*3+0], wb = w1[t*3+1], wc = w1[t*3+2], bb = b1[t];
    for (int n = 0; n < 64; n++){
        float v = fmaf(wa, sx[n*3+0], fmaf(wb, sx[n*3+1], fmaf(wc, sx[n*3+2], bb)));
        g_h1[(size_t)(n0+n)*256 + t] = __float2half_rn(gelu_exact(v));
    }
}

// ---------------------------------------------------------------------------
// fp16 mma.sync GEMM: C[M x Ntot] = epi(A[M x K] @ W[Ntot x K]^T + bias)
// Block 128x256, BK=32, 256 threads = 8 warps (2x4), warp tile 64x64.
// 4-stage cp.async pipeline, XOR-swizzled smem, ldmatrix.x4 fragment loads.
// EPI: 0=fp32 store(+bias), 1=gelu->fp16, 2=+fourier->fp16, 4=plain fp16.
// ---------------------------------------------------------------------------
#define GEMM_SMEM (96*1024)

template<int K, int EPI, bool HAS_BIAS>
__global__ __launch_bounds__(256, 1)
void gemm16(const __half* __restrict__ A, int lda,
            const __half* __restrict__ W, int ldw,
            const float* __restrict__ bias,
            void* __restrict__ Cout, int ldc,
            const float* __restrict__ pos,
            const float* __restrict__ bfour)
{
    extern __shared__ char smem[];
    const int t    = threadIdx.x;
    const int lane = t & 31;
    const int w    = t >> 5;
    const int wm   = w >> 2, wn = w & 3;          // 2 x 4 warp grid
    const int gid  = lane >> 2, tig = lane & 3;
    const int m0   = blockIdx.x * 128;
    const int n0   = blockIdx.y * 256;
    const uint32_t sb = smem_u32(smem);

    // per-lane ldmatrix base offsets (k-slice s=0 baked in; s=1 -> XOR 0x20)
    uint32_t offA[4], offB[4];
    {
        const int l8 = lane & 7;
        const int h3 = (lane >> 3) & 1;
        const int h4 = lane >> 4;
        #pragma unroll
        for (int mi = 0; mi < 4; mi++){
            int rA = wm*64 + mi*16 + h3*8 + l8;
            int sw = (rA >> 1) & 3;
            offA[mi] = (uint32_t)(rA*64) + (uint32_t)((h4 ^ sw) << 4);
        }
        #pragma unroll
        for (int p = 0; p < 4; p++){
            int rB = wn*64 + p*16 + h4*8 + l8;
            int sw = (rB >> 1) & 3;
            offB[p] = (uint32_t)(rB*64) + (uint32_t)((h3 ^ sw) << 4);
        }
    }

    float acc[4][8][4];
    #pragma unroll
    for (int i = 0; i < 4; i++)
        #pragma unroll
        for (int j = 0; j < 8; j++)
            #pragma unroll
            for (int r = 0; r < 4; r++) acc[i][j][r] = 0.f;

    constexpr int NC = K / 32;

    auto produce = [&](int kc){
        const int st = kc & 3;
        #pragma unroll
        for (int it = 0; it < 2; it++){
            const int idx = it*256 + t, r = idx >> 2, c = idx & 3;
            uint32_t dst = sb + st*8192 + r*64 + (uint32_t)((c ^ ((r>>1)&3)) << 4);
            CP16(dst, (const void*)(A + (size_t)(m0 + r)*lda + kc*32 + c*8));
        }
        #pragma unroll
        for (int it = 0; it < 4; it++){
            const int idx = it*256 + t, rr = idx >> 2, cc = idx & 3;
            uint32_t db = sb + 32768 + st*16384 + rr*64 + (uint32_t)((cc ^ ((rr>>1)&3)) << 4);
            CP16(db, (const void*)(W + (size_t)(n0 + rr)*ldw + kc*32 + cc*8));
        }
        CP_COMMIT();
    };

    produce(0); produce(1); produce(2);

    #pragma unroll 1
    for (int kc = 0; kc < NC; kc++){
        CP_WAIT2();
        __syncthreads();
        const uint32_t aB = sb + (kc & 3)*8192;
        const uint32_t bB = sb + 32768u + (kc & 3)*16384;
        #pragma unroll
        for (int s = 0; s < 2; s++){
            const uint32_t sx = (uint32_t)s << 5;
            uint32_t afr[4][4], bfr[8][2];
            #pragma unroll
            for (int mi = 0; mi < 4; mi++)
                ldsm4(afr[mi][0], afr[mi][1], afr[mi][2], afr[mi][3],
                      aB + (offA[mi] ^ sx));
            #pragma unroll
            for (int p = 0; p < 4; p++)
                ldsm4(bfr[2*p][0], bfr[2*p][1], bfr[2*p+1][0], bfr[2*p+1][1],
                      bB + (offB[p] ^ sx));
            #pragma unroll
            for (int mi = 0; mi < 4; mi++)
                #pragma unroll
                for (int nj = 0; nj < 8; nj++)
                    mma16(acc[mi][nj], afr[mi], bfr[nj]);
        }
        if (kc + 3 < NC) produce(kc + 3); else CP_COMMIT();
    }

    // ---- epilogue ----
    #pragma unroll
    for (int mi = 0; mi < 4; mi++){
        const int r0 = m0 + wm*64 + mi*16 + gid;
        const int r1 = r0 + 8;
        float p00 = 0.f, p01 = 0.f, p10 = 0.f, p11 = 0.f;
        if (EPI == 2){
            p00 = pos[(size_t)r0*2]; p01 = pos[(size_t)r0*2 + 1];
            p10 = pos[(size_t)r1*2]; p11 = pos[(size_t)r1*2 + 1];
        }
        #pragma unroll
        for (int nj = 0; nj < 8; nj++){
            const int cb = n0 + wn*64 + nj*8 + 2*tig;
            float v0 = acc[mi][nj][0], v1 = acc[mi][nj][1];
            float v2 = acc[mi][nj][2], v3 = acc[mi][nj][3];
            if (HAS_BIAS){
                const float b0 = bias[cb], b1 = bias[cb+1];
                v0 += b0; v1 += b1; v2 += b0; v3 += b1;
            }
            if (EPI == 1){
                v0 = gelu_exact(v0); v1 = gelu_exact(v1);
                v2 = gelu_exact(v2); v3 = gelu_exact(v3);
            }
            if (EPI == 2){
                const int o0 = cb & 255, o1 = (cb+1) & 255;
                const float ba0 = bfour[(o0 & 127)*2], bb0 = bfour[(o0 & 127)*2 + 1];
                const float ba1 = bfour[(o1 & 127)*2], bb1 = bfour[(o1 & 127)*2 + 1];
                const float TP = 6.283185307179586f;
                float pl0 = TP*(p00*ba0 + p01*bb0), pl1 = TP*(p00*ba1 + p01*bb1);
                float ph0 = TP*(p10*ba0 + p11*bb0), ph1 = TP*(p10*ba1 + p11*bb1);
                v0 += (o0 < 128) ? __cosf(pl0) : __sinf(pl0);
                v1 += (o1 < 128) ? __cosf(pl1) : __sinf(pl1);
                v2 += (o0 < 128) ? __cosf(ph0) : __sinf(ph0);
                v3 += (o1 < 128) ? __cosf(ph1) : __sinf(ph1);
            }
            if (EPI == 0){
                float* C = (float*)Cout;
                *(float2*)(C + (size_t)r0*ldc + cb) = make_float2(v0, v1);
                *(float2*)(C + (size_t)r1*ldc + cb) = make_float2(v2, v3);
            } else {
                __half* C = (__half*)Cout;
                *(__half2*)(C + (size_t)r0*ldc + cb) = __floats2half2_rn(v0, v1);
                *(__half2*)(C + (size_t)r1*ldc + cb) = __floats2half2_rn(v2, v3);
            }
        }
    }
}

// ---------------------------------------------------------------------------
// Fused edge kernel: per block of 128 edges (= 8 dsts):
//   phase 1: m2 = gelu([gelu(ea[src]+eb[dst])] @ W2^T + b2)   (K=512)  -> SMEM
//   phase 2: m3 = m2 @ W3^T + b3 ; out[dst] = mean_16(m3)     (K=256)
// ---------------------------------------------------------------------------
__global__ __launch_bounds__(256, 1)
void edge_fused(const __half* __restrict__ eaH, const float* __restrict__ ebF,
                const __half* __restrict__ W2, const float* __restrict__ b2,
                const __half* __restrict__ W3, const float* __restrict__ b3,
                float* __restrict__ out, const int* __restrict__ me32)
{
    extern __shared__ char smem[];
    __shared__ int sSrc[128], sDst[128];
    const int t    = threadIdx.x;
    const int lane = t & 31;
    const int w    = t >> 5;
    const int wm   = w >> 2, wn = w & 3;          // 2 x 4 warp grid
    const int gid  = lane >> 2, tig = lane & 3;
    const int m0   = blockIdx.x * 128;
    const uint32_t sb = smem_u32(smem);

    if (t < 128){
        const int e = m0 + t; int s, d;
        if (g_is64){ d = me32[4*e]; s = me32[4*e+2]; }
        else       { d = me32[2*e]; s = me32[2*e+1]; }
        sSrc[t] = s; sDst[t] = d;
    }
    __syncthreads();

    // per-lane ldmatrix offsets
    uint32_t offA[4], offB[4], baseM[4];
    int swM[4];
    const int l8 = lane & 7;
    const int h3 = (lane >> 3) & 1;
    const int h4 = lane >> 4;
    #pragma unroll
    for (int mi = 0; mi < 4; mi++){
        int rA = wm*64 + mi*16 + h3*8 + l8;
        int sw = (rA >> 1) & 3;
        offA[mi] = (uint32_t)(rA*64) + (uint32_t)((h4 ^ sw) << 4);
        baseM[mi] = 32768u + (uint32_t)(rA*512);
        swM[mi] = rA & 7;
    }
    #pragma unroll
    for (int p = 0; p < 4; p++){
        int rB = wn*64 + p*16 + h4*8 + l8;
        int sw = (rB >> 1) & 3;
        offB[p] = (uint32_t)(rB*64) + (uint32_t)((h3 ^ sw) << 4);
    }

    float acc[4][8][4];
    #pragma unroll
    for (int i = 0; i < 4; i++)
        #pragma unroll
        for (int j = 0; j < 8; j++)
            #pragma unroll
            for (int r = 0; r < 4; r++) acc[i][j][r] = 0.f;

    // ---- phase 1 producer: A = gelu(ea[src]+eb[dst]) (STS), B = W2 (cp.async)
    auto produce1 = [&](int kc){
        const int st = kc & 3;
        #pragma unroll
        for (int it = 0; it < 2; it++){
            const int idx = it*256 + t;
            const int r = idx >> 2, c = idx & 3;
            const int k0 = kc*32 + c*8;
            uint4 av = *(const uint4*)(eaH + (size_t)sSrc[r]*512 + k0);
            const float* pb = ebF + (size_t)sDst[r]*512 + k0;
            float4 e0 = *(const float4*)pb, e1 = *(const float4*)(pb + 4);
            const __half2* ah = (const __half2*)&av;
            float2 f0 = __half22float2(ah[0]), f1 = __half22float2(ah[1]);
            float2 f2 = __half22float2(ah[2]), f3 = __half22float2(ah[3]);
            __half2 h0 = __floats2half2_rn(gelu_exact(f0.x+e0.x), gelu_exact(f0.y+e0.y));
            __half2 h1 = __floats2half2_rn(gelu_exact(f1.x+e0.z), gelu_exact(f1.y+e0.w));
            __half2 h2 = __floats2half2_rn(gelu_exact(f2.x+e1.x), gelu_exact(f2.y+e1.y));
            __half2 h3v = __floats2half2_rn(gelu_exact(f3.x+e1.z), gelu_exact(f3.y+e1.w));
            uint4 pk;
            pk.x = *reinterpret_cast<uint32_t*>(&h0);
            pk.y = *reinterpret_cast<uint32_t*>(&h1);
            pk.z = *reinterpret_cast<uint32_t*>(&h2);
            pk.w = *reinterpret_cast<uint32_t*>(&h3v);
            *(uint4*)(smem + st*8192 + r*64 + ((c ^ ((r>>1)&3)) << 4)) = pk;
        }
        #pragma unroll
        for (int it = 0; it < 4; it++){
            const int idx = it*256 + t, rr = idx >> 2, cc = idx & 3;
            uint32_t db = sb + 32768 + st*16384 + rr*64 + (uint32_t)((cc ^ ((rr>>1)&3)) << 4);
            CP16(db, (const void*)(W2 + (size_t)rr*512 + kc*32 + cc*8));
        }
        CP_COMMIT();
    };

    produce1(0); produce1(1); produce1(2);

    #pragma unroll 1
    for (int kc = 0; kc < 16; kc++){
        CP_WAIT2();
        __syncthreads();
        const uint32_t aB = sb + (kc & 3)*8192;
        const uint32_t bB = sb + 32768u + (kc & 3)*16384;
        #pragma unroll
        for (int s = 0; s < 2; s++){
            const uint32_t sx = (uint32_t)s << 5;
            uint32_t afr[4][4], bfr[8][2];
            #pragma unroll
            for (int mi = 0; mi < 4; mi++)
                ldsm4(afr[mi][0], afr[mi][1], afr[mi][2], afr[mi][3],
                      aB + (offA[mi] ^ sx));
            #pragma unroll
            for (int p = 0; p < 4; p++)
                ldsm4(bfr[2*p][0], bfr[2*p][1], bfr[2*p+1][0], bfr[2*p+1][1],
                      bB + (offB[p] ^ sx));
            #pragma unroll
            for (int mi = 0; mi < 4; mi++)
                #pragma unroll
                for (int nj = 0; nj < 8; nj++)
                    mma16(acc[mi][nj], afr[mi], bfr[nj]);
        }
        if (kc + 3 < 16) produce1(kc + 3); else CP_COMMIT();
    }

    __syncthreads();   // everyone done with phase-1 tiles

    // ---- phase 2 W3 producer into [0,32KB), 2 stages
    auto produce2 = [&](int kc){
        const int st = kc & 1;
        #pragma unroll
        for (int it = 0; it < 4; it++){
            const int idx = it*256 + t, rr = idx >> 2, cc = idx & 3;
            uint32_t db = sb + st*16384 + rr*64 + (uint32_t)((cc ^ ((rr>>1)&3)) << 4);
            CP16(db, (const void*)(W3 + (size_t)rr*256 + kc*32 + cc*8));
        }
        CP_COMMIT();
    };
    produce2(0);

    // ---- epilogue-1: m2 = gelu(acc + b2) -> fp16 SMEM at [32KB, 96KB)
    #pragma unroll
    for (int mi = 0; mi < 4; mi++){
        const int lr0 = wm*64 + mi*16 + gid;
        const int lr1 = lr0 + 8;
        #pragma unroll
        for (int nj = 0; nj < 8; nj++){
            const int cb = wn*64 + nj*8 + 2*tig;
            const float b0 = b2[cb], b1 = b2[cb+1];
            __half2 lo = __floats2half2_rn(gelu_exact(acc[mi][nj][0] + b0),
                                           gelu_exact(acc[mi][nj][1] + b1));
            __half2 hi = __floats2half2_rn(gelu_exact(acc[mi][nj][2] + b0),
                                           gelu_exact(acc[mi][nj][3] + b1));
            const int blk = cb >> 3;
            *(__half2*)(smem + 32768 + lr0*512 + ((blk ^ (lr0 & 7)) << 4) + 4*tig) = lo;
            *(__half2*)(smem + 32768 + lr1*512 + ((blk ^ (lr1 & 7)) << 4) + 4*tig) = hi;
            acc[mi][nj][0] = 0.f; acc[mi][nj][1] = 0.f;
            acc[mi][nj][2] = 0.f; acc[mi][nj][3] = 0.f;
        }
    }

    // ---- phase 2 main loop (K=256, 8 chunks)
    #pragma unroll 1
    for (int kc = 0; kc < 8; kc++){
        __syncthreads();                 // prev compute done; m2 visible (kc=0)
        if (kc + 1 < 8) produce2(kc + 1); else CP_COMMIT();
        CP_WAIT1();
        __syncthreads();
        const uint32_t bB = sb + (kc & 1)*16384;
        #pragma unroll
        for (int s = 0; s < 2; s++){
            const uint32_t sx = (uint32_t)s << 5;
            uint32_t afr[4][4], bfr[8][2];
            #pragma unroll
            for (int mi = 0; mi < 4; mi++){
                const int blk = kc*4 + h4;
                const uint32_t offM = (uint32_t)((blk ^ swM[mi]) << 4);
                ldsm4(afr[mi][0], afr[mi][1], afr[mi][2], afr[mi][3],
                      sb + baseM[mi] + (offM ^ sx));
            }
            #pragma unroll
            for (int p = 0; p < 4; p++)
                ldsm4(bfr[2*p][0], bfr[2*p][1], bfr[2*p+1][0], bfr[2*p+1][1],
                      bB + (offB[p] ^ sx));
            #pragma unroll
            for (int mi = 0; mi < 4; mi++)
                #pragma unroll
                for (int nj = 0; nj < 8; nj++)
                    mma16(acc[mi][nj], afr[mi], bfr[nj]);
        }
    }

    // ---- final epilogue: segment mean over 16 edges + b3
    #pragma unroll
    for (int mi = 0; mi < 4; mi++){
        #pragma unroll
        for (int nj = 0; nj < 8; nj++){
            const int cb = wn*64 + nj*8 + 2*tig;
            float s0 = acc[mi][nj][0] + acc[mi][nj][2];
            float s1 = acc[mi][nj][1] + acc[mi][nj][3];
            s0 += __shfl_xor_sync(0xffffffffu, s0, 4);
            s0 += __shfl_xor_sync(0xffffffffu, s0, 8);
            s0 += __shfl_xor_sync(0xffffffffu, s0, 16);
            s1 += __shfl_xor_sync(0xffffffffu, s1, 4);
            s1 += __shfl_xor_sync(0xffffffffu, s1, 8);
            s1 += __shfl_xor_sync(0xffffffffu, s1, 16);
            if (lane < 4){
                const int dst = (m0 + wm*64 + mi*16) >> 4;
                float2 o;
                o.x = s0 * 0.0625f + b3[cb];
                o.y = s1 * 0.0625f + b3[cb+1];
                *(float2*)(out + (size_t)dst*256 + cb) = o;
            }
        }
    }
}

// ---------------------------------------------------------------------------
extern "C" void kernel_launch(void* const* d_in, const int* in_sizes, int n_in,
                              void* d_out, int out_size)
{
    const float* x        = (const float*)d_in[0];
    const float* mesh_pos = (const float*)d_in[1];
    const int*   me32     = (const int*)  d_in[2];
    const float* ip_w1 = (const float*)d_in[4];
    const float* ip_b1 = (const float*)d_in[5];
    const float* ip_w2 = (const float*)d_in[6];
    const float* ip_b2 = (const float*)d_in[7];
    const float* ip_w3 = (const float*)d_in[8];
    const float* ip_b3 = (const float*)d_in[9];
    const float* bf    = (const float*)d_in[10];
    const float* mw1   = (const float*)d_in[11];
    const float* mb1   = (const float*)d_in[12];
    const float* mw2   = (const float*)d_in[13];
    const float* mb2   = (const float*)d_in[14];
    const float* mw3   = (const float*)d_in[15];
    const float* mb3   = (const float*)d_in[16];
    float* out = (float*)d_out;

    __half *h1p, *h2p, *hhp, *eaHp, *w2h, *w3h, *mw1h, *mw2h, *mw3h;
    float  *ebp;
    cudaGetSymbolAddress((void**)&h1p,  g_h1);
    cudaGetSymbolAddress((void**)&h2p,  g_h2a);
    cudaGetSymbolAddress((void**)&hhp,  g_hh);
    cudaGetSymbolAddress((void**)&eaHp, g_eaH);
    cudaGetSymbolAddress((void**)&ebp,  g_eb);
    cudaGetSymbolAddress((void**)&w2h,  g_w2h);
    cudaGetSymbolAddress((void**)&w3h,  g_w3h);
    cudaGetSymbolAddress((void**)&mw1h, g_mw1h);
    cudaGetSymbolAddress((void**)&mw2h, g_mw2h);
    cudaGetSymbolAddress((void**)&mw3h, g_mw3h);

    cudaFuncSetAttribute(gemm16<256,1,true >, cudaFuncAttributeMaxDynamicSharedMemorySize, GEMM_SMEM);
    cudaFuncSetAttribute(gemm16<256,2,true >, cudaFuncAttributeMaxDynamicSharedMemorySize, GEMM_SMEM);
    cudaFuncSetAttribute(gemm16<256,4,false>, cudaFuncAttributeMaxDynamicSharedMemorySize, GEMM_SMEM);
    cudaFuncSetAttribute(gemm16<256,0,true >, cudaFuncAttributeMaxDynamicSharedMemorySize, GEMM_SMEM);
    cudaFuncSetAttribute(edge_fused,          cudaFuncAttributeMaxDynamicSharedMemorySize, GEMM_SMEM);

    detect_kernel<<<1, 32>>>(me32);

    // single fp16 weight prep launch
    f2h_all<<<576, 256>>>(ip_w2, ip_w3, mw1, mw2, mw3, w2h, w3h, mw1h, mw2h, mw3h);

    // node encoder
    h1_kernel<<<N_NODES/64, 256>>>(x, ip_w1, ip_b1);
    gemm16<256,1,true ><<<dim3(N_NODES/128,1), 256, GEMM_SMEM>>>(
        h1p, 256, w2h, 256, ip_b2, h2p, 256, nullptr, nullptr);
    gemm16<256,2,true ><<<dim3(N_NODES/128,1), 256, GEMM_SMEM>>>(
        h2p, 256, w3h, 256, ip_b3, hhp, 256, mesh_pos, bf);

    // hoisted edge layer-1 halves: ea fp16 (no bias), eb fp32 (+b1)
    gemm16<256,4,false><<<dim3(N_NODES/128,2), 256, GEMM_SMEM>>>(
        hhp, 256, mw1h, 512, nullptr, eaHp, 512, nullptr, nullptr);
    gemm16<256,0,true ><<<dim3(N_DST/128,2), 256, GEMM_SMEM>>>(
        hhp, 256, mw1h + 256, 512, mb1, ebp, 512, nullptr, nullptr);

    // fused edge layers 2+3 + segment mean
    edge_fused<<<N_EDGES/128, 256, GEMM_SMEM>>>(
        eaHp, ebp, mw2h, mb2, mw3h, mb3, out, me32);
}

// round 8
// speedup vs baseline: 1.2193x; 1.2193x over previous
#include <cuda_runtime.h>
#include <cuda_fp16.h>
#include <math.h>
#include <stdint.h>

#define N_NODES 131072
#define N_DST   16384
#define DEG     16
#define N_EDGES (N_DST*DEG)
#define HID     256

// ---------------- global scratch (device globals: no runtime alloc) --------
__device__ __align__(16) __half g_h1 [(size_t)N_NODES * 256];
__device__ __align__(16) __half g_h2a[(size_t)N_NODES * 256];
__device__ __align__(16) __half g_hh [(size_t)N_NODES * 256];
__device__ __align__(16) __half g_eaH[(size_t)N_NODES * 512];
__device__ __align__(16) float  g_eb [(size_t)N_DST   * 512];
__device__ __align__(16) __half g_w2h [256*256];
__device__ __align__(16) __half g_w3h [256*256];
__device__ __align__(16) __half g_mw1h[512*512];
__device__ __align__(16) __half g_mw2h[256*512];
__device__ __align__(16) __half g_mw3h[256*256];
__device__ int g_is64;

__device__ __forceinline__ float gelu_exact(float x){
    return 0.5f * x * (1.0f + erff(x * 0.70710678118654752f));
}
__device__ __forceinline__ uint32_t smem_u32(const void* p){
    uint32_t a;
    asm("{ .reg .u64 t; cvta.to.shared.u64 t, %1; cvt.u32.u64 %0, t; }" : "=r"(a) : "l"(p));
    return a;
}
__device__ __forceinline__ void mma16(float* c, const uint32_t* a, const uint32_t* b){
    asm volatile("mma.sync.aligned.m16n8k16.row.col.f32.f16.f16.f32 "
        "{%0,%1,%2,%3}, {%4,%5,%6,%7}, {%8,%9}, {%0,%1,%2,%3};"
        : "+f"(c[0]), "+f"(c[1]), "+f"(c[2]), "+f"(c[3])
        : "r"(a[0]), "r"(a[1]), "r"(a[2]), "r"(a[3]), "r"(b[0]), "r"(b[1]));
}
__device__ __forceinline__ void ldsm4(uint32_t& r0, uint32_t& r1, uint32_t& r2, uint32_t& r3,
                                      uint32_t addr){
    asm volatile("ldmatrix.sync.aligned.m8n8.x4.shared.b16 {%0,%1,%2,%3}, [%4];"
        : "=r"(r0), "=r"(r1), "=r"(r2), "=r"(r3) : "r"(addr));
}
#define CP16(dst, src) \
    asm volatile("cp.async.ca.shared.global [%0], [%1], 16;" :: "r"(dst), "l"(src) : "memory")
#define CP_COMMIT() asm volatile("cp.async.commit_group;" ::: "memory")
#define CP_WAIT2()  asm volatile("cp.async.wait_group 2;"  ::: "memory")
#define CP_WAIT1()  asm volatile("cp.async.wait_group 1;"  ::: "memory")

// ---------------------------------------------------------------------------
__global__ void detect_kernel(const int* __restrict__ me32){
    if (threadIdx.x == 0 && blockIdx.x == 0) g_is64 = (me32[32] != 1) ? 1 : 0;
}

// one-shot fp16 conversion of all five weight matrices (float4 granularity)
__global__ __launch_bounds__(256)
void f2h_all(const float* __restrict__ w2, const float* __restrict__ w3,
             const float* __restrict__ m1, const float* __restrict__ m2,
             const float* __restrict__ m3,
             __half* __restrict__ dw2, __half* __restrict__ dw3,
             __half* __restrict__ dm1, __half* __restrict__ dm2,
             __half* __restrict__ dm3)
{
    int i = blockIdx.x*256 + threadIdx.x;          // float4 index, total 147456
    const float* s; __half* d; int off;
    if      (i <  16384){ s = w2; d = dw2; off = i; }
    else if (i <  32768){ s = w3; d = dw3; off = i - 16384; }
    else if (i <  98304){ s = m1; d = dm1; off = i - 32768; }
    else if (i < 131072){ s = m2; d = dm2; off = i - 98304; }
    else                { s = m3; d = dm3; off = i - 131072; }
    float4 v = ((const float4*)s)[off];
    __half2 h0 = __floats2half2_rn(v.x, v.y), h1 = __floats2half2_rn(v.z, v.w);
    uint2 pk;
    pk.x = *reinterpret_cast<uint32_t*>(&h0);
    pk.y = *reinterpret_cast<uint32_t*>(&h1);
    ((uint2*)d)[off] = pk;
}

// h1 = gelu(x @ W1^T + b1), K=3: fp32 math, fp16 store.
__global__ __launch_bounds__(256)
void h1_kernel(const float* __restrict__ x,
               const float* __restrict__ w1, const float* __restrict__ b1){
    __shared__ float sx[64*3];
    const int t  = threadIdx.x;
    const int n0 = blockIdx.x * 64;
    for (int i = t; i < 64*3; i += 256) sx[i] = x[(size_t)n0*3 + i];
    __syncthreads();
    const float wa = w1[t*3+0], wb = w1[t*3+1], wc = w1[t*3+2], bb = b1[t];
    for (int n = 0; n < 64; n++){
        float v = fmaf(wa, sx[n*3+0], fmaf(wb, sx[n*3+1], fmaf(wc, sx[n*3+2], bb)));
        g_h1[(size_t)(n0+n)*256 + t] = __float2half_rn(gelu_exact(v));
    }
}

// ---------------------------------------------------------------------------
// fp16 mma.sync GEMM: C[M x Ntot] = epi(A[M x K] @ W[Ntot x K]^T + bias)
// Block 128x128, BK=32, 256 threads = 8 warps (4m x 2n), warp tile 32x64.
// 4-stage cp.async, 64KB smem, 2 CTAs/SM (latency hiding across CTAs).
// EPI: 0=fp32 store(+bias), 1=gelu->fp16, 2=+fourier->fp16, 4=plain fp16.
// ---------------------------------------------------------------------------
#define GEMM_SMEM (64*1024)

template<int K, int EPI, bool HAS_BIAS>
__global__ __launch_bounds__(256, 2)
void gemm16(const __half* __restrict__ A, int lda,
            const __half* __restrict__ W, int ldw,
            const float* __restrict__ bias,
            void* __restrict__ Cout, int ldc,
            const float* __restrict__ pos,
            const float* __restrict__ bfour)
{
    extern __shared__ char smem[];
    const int t    = threadIdx.x;
    const int lane = t & 31;
    const int w    = t >> 5;
    const int wm   = w >> 1, wn = w & 1;          // 4 x 2 warp grid
    const int gid  = lane >> 2, tig = lane & 3;
    const int m0   = blockIdx.x * 128;
    const int n0   = blockIdx.y * 128;
    const uint32_t sb = smem_u32(smem);

    // per-lane ldmatrix base offsets (k-slice s=0 baked in; s=1 -> XOR 0x20)
    uint32_t offA[2], offB[4];
    {
        const int l8 = lane & 7;
        const int h3 = (lane >> 3) & 1;
        const int h4 = lane >> 4;
        #pragma unroll
        for (int mi = 0; mi < 2; mi++){
            int rA = wm*32 + mi*16 + h3*8 + l8;
            int sw = (rA >> 1) & 3;
            offA[mi] = (uint32_t)(rA*64) + (uint32_t)((h4 ^ sw) << 4);
        }
        #pragma unroll
        for (int p = 0; p < 4; p++){
            int rB = wn*64 + p*16 + h4*8 + l8;
            int sw = (rB >> 1) & 3;
            offB[p] = (uint32_t)(rB*64) + (uint32_t)((h3 ^ sw) << 4);
        }
    }

    float acc[2][8][4];
    #pragma unroll
    for (int i = 0; i < 2; i++)
        #pragma unroll
        for (int j = 0; j < 8; j++)
            #pragma unroll
            for (int r = 0; r < 4; r++) acc[i][j][r] = 0.f;

    constexpr int NC = K / 32;

    auto produce = [&](int kc){
        const int st = kc & 3;
        #pragma unroll
        for (int it = 0; it < 2; it++){
            const int idx = it*256 + t, r = idx >> 2, c = idx & 3;
            uint32_t dst = sb + st*8192 + r*64 + (uint32_t)((c ^ ((r>>1)&3)) << 4);
            CP16(dst, (const void*)(A + (size_t)(m0 + r)*lda + kc*32 + c*8));
        }
        #pragma unroll
        for (int it = 0; it < 2; it++){
            const int idx = it*256 + t, rr = idx >> 2, cc = idx & 3;
            uint32_t db = sb + 32768 + st*8192 + rr*64 + (uint32_t)((cc ^ ((rr>>1)&3)) << 4);
            CP16(db, (const void*)(W + (size_t)(n0 + rr)*ldw + kc*32 + cc*8));
        }
        CP_COMMIT();
    };

    produce(0); produce(1); produce(2);

    #pragma unroll 1
    for (int kc = 0; kc < NC; kc++){
        CP_WAIT2();
        __syncthreads();
        const uint32_t aB = sb + (kc & 3)*8192;
        const uint32_t bB = sb + 32768u + (kc & 3)*8192;
        #pragma unroll
        for (int s = 0; s < 2; s++){
            const uint32_t sx = (uint32_t)s << 5;
            uint32_t afr[2][4], bfr[8][2];
            #pragma unroll
            for (int mi = 0; mi < 2; mi++)
                ldsm4(afr[mi][0], afr[mi][1], afr[mi][2], afr[mi][3],
                      aB + (offA[mi] ^ sx));
            #pragma unroll
            for (int p = 0; p < 4; p++)
                ldsm4(bfr[2*p][0], bfr[2*p][1], bfr[2*p+1][0], bfr[2*p+1][1],
                      bB + (offB[p] ^ sx));
            #pragma unroll
            for (int mi = 0; mi < 2; mi++)
                #pragma unroll
                for (int nj = 0; nj < 8; nj++)
                    mma16(acc[mi][nj], afr[mi], bfr[nj]);
        }
        if (kc + 3 < NC) produce(kc + 3); else CP_COMMIT();
    }

    // ---- epilogue ----
    #pragma unroll
    for (int mi = 0; mi < 2; mi++){
        const int r0 = m0 + wm*32 + mi*16 + gid;
        const int r1 = r0 + 8;
        float p00 = 0.f, p01 = 0.f, p10 = 0.f, p11 = 0.f;
        if (EPI == 2){
            p00 = pos[(size_t)r0*2]; p01 = pos[(size_t)r0*2 + 1];
            p10 = pos[(size_t)r1*2]; p11 = pos[(size_t)r1*2 + 1];
        }
        #pragma unroll
        for (int nj = 0; nj < 8; nj++){
            const int cb = n0 + wn*64 + nj*8 + 2*tig;
            float v0 = acc[mi][nj][0], v1 = acc[mi][nj][1];
            float v2 = acc[mi][nj][2], v3 = acc[mi][nj][3];
            if (HAS_BIAS){
                const float b0 = bias[cb], b1 = bias[cb+1];
                v0 += b0; v1 += b1; v2 += b0; v3 += b1;
            }
            if (EPI == 1){
                v0 = gelu_exact(v0); v1 = gelu_exact(v1);
                v2 = gelu_exact(v2); v3 = gelu_exact(v3);
            }
            if (EPI == 2){
                const int o0 = cb & 255, o1 = (cb+1) & 255;
                const float ba0 = bfour[(o0 & 127)*2], bb0 = bfour[(o0 & 127)*2 + 1];
                const float ba1 = bfour[(o1 & 127)*2], bb1 = bfour[(o1 & 127)*2 + 1];
                const float TP = 6.283185307179586f;
                float pl0 = TP*(p00*ba0 + p01*bb0), pl1 = TP*(p00*ba1 + p01*bb1);
                float ph0 = TP*(p10*ba0 + p11*bb0), ph1 = TP*(p10*ba1 + p11*bb1);
                v0 += (o0 < 128) ? __cosf(pl0) : __sinf(pl0);
                v1 += (o1 < 128) ? __cosf(pl1) : __sinf(pl1);
                v2 += (o0 < 128) ? __cosf(ph0) : __sinf(ph0);
                v3 += (o1 < 128) ? __cosf(ph1) : __sinf(ph1);
            }
            if (EPI == 0){
                float* C = (float*)Cout;
                *(float2*)(C + (size_t)r0*ldc + cb) = make_float2(v0, v1);
                *(float2*)(C + (size_t)r1*ldc + cb) = make_float2(v2, v3);
            } else {
                __half* C = (__half*)Cout;
                *(__half2*)(C + (size_t)r0*ldc + cb) = __floats2half2_rn(v0, v1);
                *(__half2*)(C + (size_t)r1*ldc + cb) = __floats2half2_rn(v2, v3);
            }
        }
    }
}

// ---------------------------------------------------------------------------
// Fused edge kernel, 2 CTAs/SM: per block of 64 edges (= 4 dsts):
//   phase 1: m2 = gelu([gelu(ea[src]+eb[dst])] @ W2^T + b2)  (K=512)  -> SMEM
//   phase 2: m3 = m2 @ W3^T + b3 ; out[dst] = mean_16(m3)    (K=256)
// SMEM 64KB: ph1: W2 3x16KB at [0,48K), A 3x4KB at [48K,60K);
//            ph2: m2 64x512B at [0,32K), W3 2x16KB at [32K,64K).
// ---------------------------------------------------------------------------
#define EDGE_SMEM (64*1024)

__global__ __launch_bounds__(256, 2)
void edge_fused(const __half* __restrict__ eaH, const float* __restrict__ ebF,
                const __half* __restrict__ W2, const float* __restrict__ b2,
                const __half* __restrict__ W3, const float* __restrict__ b3,
                float* __restrict__ out, const int* __restrict__ me32)
{
    extern __shared__ char smem[];
    __shared__ int sSrc[64], sDst[64];
    const int t    = threadIdx.x;
    const int lane = t & 31;
    const int w    = t >> 5;
    const int wm   = w >> 2, wn = w & 3;          // 2 x 4 warp grid
    const int gid  = lane >> 2, tig = lane & 3;
    const int m0   = blockIdx.x * 64;
    const uint32_t sb = smem_u32(smem);

    if (t < 64){
        const int e = m0 + t; int s, d;
        if (g_is64){ d = me32[4*e]; s = me32[4*e+2]; }
        else       { d = me32[2*e]; s = me32[2*e+1]; }
        sSrc[t] = s; sDst[t] = d;
    }
    __syncthreads();

    // per-lane ldmatrix offsets
    uint32_t offA[2], offB[4], baseM[2];
    int swM[2];
    const int l8 = lane & 7;
    const int h3 = (lane >> 3) & 1;
    const int h4 = lane >> 4;
    #pragma unroll
    for (int mi = 0; mi < 2; mi++){
        int rA = wm*32 + mi*16 + h3*8 + l8;          // 0..63
        int sw = (rA >> 1) & 3;
        offA[mi] = (uint32_t)(rA*64) + (uint32_t)((h4 ^ sw) << 4);
        baseM[mi] = (uint32_t)(rA*512);
        swM[mi] = rA & 7;
    }
    #pragma unroll
    for (int p = 0; p < 4; p++){
        int rB = wn*64 + p*16 + h4*8 + l8;           // 0..255
        int sw = (rB >> 1) & 3;
        offB[p] = (uint32_t)(rB*64) + (uint32_t)((h3 ^ sw) << 4);
    }

    float acc[2][8][4];
    #pragma unroll
    for (int i = 0; i < 2; i++)
        #pragma unroll
        for (int j = 0; j < 8; j++)
            #pragma unroll
            for (int r = 0; r < 4; r++) acc[i][j][r] = 0.f;

    // ---- phase 1 producer: A = gelu(ea[src]+eb[dst]) (STS), B = W2 (cp.async)
    auto produce1 = [&](int kc, int st){
        const int r = t >> 2, c = t & 3;             // r: 0..63
        const int k0 = kc*32 + c*8;
        uint4 av = *(const uint4*)(eaH + (size_t)sSrc[r]*512 + k0);
        const float* pb = ebF + (size_t)sDst[r]*512 + k0;
        float4 e0 = *(const float4*)pb, e1 = *(const float4*)(pb + 4);
        const __half2* ah = (const __half2*)&av;
        float2 f0 = __half22float2(ah[0]), f1 = __half22float2(ah[1]);
        float2 f2 = __half22float2(ah[2]), f3 = __half22float2(ah[3]);
        __half2 h0 = __floats2half2_rn(gelu_exact(f0.x+e0.x), gelu_exact(f0.y+e0.y));
        __half2 h1 = __floats2half2_rn(gelu_exact(f1.x+e0.z), gelu_exact(f1.y+e0.w));
        __half2 h2 = __floats2half2_rn(gelu_exact(f2.x+e1.x), gelu_exact(f2.y+e1.y));
        __half2 h3v = __floats2half2_rn(gelu_exact(f3.x+e1.z), gelu_exact(f3.y+e1.w));
        uint4 pk;
        pk.x = *reinterpret_cast<uint32_t*>(&h0);
        pk.y = *reinterpret_cast<uint32_t*>(&h1);
        pk.z = *reinterpret_cast<uint32_t*>(&h2);
        pk.w = *reinterpret_cast<uint32_t*>(&h3v);
        *(uint4*)(smem + 49152 + st*4096 + r*64 + ((c ^ ((r>>1)&3)) << 4)) = pk;
        #pragma unroll
        for (int it = 0; it < 4; it++){
            const int idx = it*256 + t, rr = idx >> 2, cc = idx & 3;
            uint32_t db = sb + st*16384 + rr*64 + (uint32_t)((cc ^ ((rr>>1)&3)) << 4);
            CP16(db, (const void*)(W2 + (size_t)rr*512 + kc*32 + cc*8));
        }
        CP_COMMIT();
    };

    produce1(0, 0); produce1(1, 1);

    int ccur = 0, pcur = 2;
    #pragma unroll 1
    for (int kc = 0; kc < 16; kc++){
        CP_WAIT1();
        __syncthreads();
        const uint32_t aB = sb + 49152u + ccur*4096;
        const uint32_t bB = sb + ccur*16384;
        #pragma unroll
        for (int s = 0; s < 2; s++){
            const uint32_t sx = (uint32_t)s << 5;
            uint32_t afr[2][4], bfr[8][2];
            #pragma unroll
            for (int mi = 0; mi < 2; mi++)
                ldsm4(afr[mi][0], afr[mi][1], afr[mi][2], afr[mi][3],
                      aB + (offA[mi] ^ sx));
            #pragma unroll
            for (int p = 0; p < 4; p++)
                ldsm4(bfr[2*p][0], bfr[2*p][1], bfr[2*p+1][0], bfr[2*p+1][1],
                      bB + (offB[p] ^ sx));
            #pragma unroll
            for (int mi = 0; mi < 2; mi++)
                #pragma unroll
                for (int nj = 0; nj < 8; nj++)
                    mma16(acc[mi][nj], afr[mi], bfr[nj]);
        }
        if (kc + 2 < 16) produce1(kc + 2, pcur); else CP_COMMIT();
        ccur = (ccur == 2) ? 0 : ccur + 1;
        pcur = (pcur == 2) ? 0 : pcur + 1;
    }

    __syncthreads();   // everyone done reading phase-1 tiles

    // ---- phase 2 W3 producer into [32K,64K), 2 stages
    auto produce2 = [&](int kc){
        const int st = kc & 1;
        #pragma unroll
        for (int it = 0; it < 4; it++){
            const int idx = it*256 + t, rr = idx >> 2, cc = idx & 3;
            uint32_t db = sb + 32768 + st*16384 + rr*64 + (uint32_t)((cc ^ ((rr>>1)&3)) << 4);
            CP16(db, (const void*)(W3 + (size_t)rr*256 + kc*32 + cc*8));
        }
        CP_COMMIT();
    };
    produce2(0);

    // ---- epilogue-1: m2 = gelu(acc + b2) -> fp16 SMEM at [0, 32K)
    #pragma unroll
    for (int mi = 0; mi < 2; mi++){
        const int lr0 = wm*32 + mi*16 + gid;
        const int lr1 = lr0 + 8;
        #pragma unroll
        for (int nj = 0; nj < 8; nj++){
            const int cb = wn*64 + nj*8 + 2*tig;
            const float b0 = b2[cb], b1 = b2[cb+1];
            __half2 lo = __floats2half2_rn(gelu_exact(acc[mi][nj][0] + b0),
                                           gelu_exact(acc[mi][nj][1] + b1));
            __half2 hi = __floats2half2_rn(gelu_exact(acc[mi][nj][2] + b0),
                                           gelu_exact(acc[mi][nj][3] + b1));
            const int blk = cb >> 3;
            *(__half2*)(smem + lr0*512 + ((blk ^ (lr0 & 7)) << 4) + 4*tig) = lo;
            *(__half2*)(smem + lr1*512 + ((blk ^ (lr1 & 7)) << 4) + 4*tig) = hi;
            acc[mi][nj][0] = 0.f; acc[mi][nj][1] = 0.f;
            acc[mi][nj][2] = 0.f; acc[mi][nj][3] = 0.f;
        }
    }

    // ---- phase 2 main loop (K=256, 8 chunks)
    #pragma unroll 1
    for (int kc = 0; kc < 8; kc++){
        __syncthreads();                 // prev compute done; m2 visible (kc=0)
        if (kc + 1 < 8) produce2(kc + 1); else CP_COMMIT();
        CP_WAIT1();
        __syncthreads();
        const uint32_t bB = sb + 32768u + (kc & 1)*16384;
        #pragma unroll
        for (int s = 0; s < 2; s++){
            const uint32_t sx = (uint32_t)s << 5;
            uint32_t afr[2][4], bfr[8][2];
            #pragma unroll
            for (int mi = 0; mi < 2; mi++){
                const int blk = kc*4 + h4;
                const uint32_t offM = (uint32_t)((blk ^ swM[mi]) << 4);
                ldsm4(afr[mi][0], afr[mi][1], afr[mi][2], afr[mi][3],
                      sb + baseM[mi] + (offM ^ sx));
            }
            #pragma unroll
            for (int p = 0; p < 4; p++)
                ldsm4(bfr[2*p][0], bfr[2*p][1], bfr[2*p+1][0], bfr[2*p+1][1],
                      bB + (offB[p] ^ sx));
            #pragma unroll
            for (int mi = 0; mi < 2; mi++)
                #pragma unroll
                for (int nj = 0; nj < 8; nj++)
                    mma16(acc[mi][nj], afr[mi], bfr[nj]);
        }
    }

    // ---- final epilogue: segment mean over 16 edges + b3
    #pragma unroll
    for (int mi = 0; mi < 2; mi++){
        #pragma unroll
        for (int nj = 0; nj < 8; nj++){
            const int cb = wn*64 + nj*8 + 2*tig;
            float s0 = acc[mi][nj][0] + acc[mi][nj][2];
            float s1 = acc[mi][nj][1] + acc[mi][nj][3];
            s0 += __shfl_xor_sync(0xffffffffu, s0, 4);
            s0 += __shfl_xor_sync(0xffffffffu, s0, 8);
            s0 += __shfl_xor_sync(0xffffffffu, s0, 16);
            s1 += __shfl_xor_sync(0xffffffffu, s1, 4);
            s1 += __shfl_xor_sync(0xffffffffu, s1, 8);
            s1 += __shfl_xor_sync(0xffffffffu, s1, 16);
            if (lane < 4){
                const int dst = (m0 + wm*32 + mi*16) >> 4;
                float2 o;
                o.x = s0 * 0.0625f + b3[cb];
                o.y = s1 * 0.0625f + b3[cb+1];
                *(float2*)(out + (size_t)dst*256 + cb) = o;
            }
        }
    }
}

// ---------------------------------------------------------------------------
extern "C" void kernel_launch(void* const* d_in, const int* in_sizes, int n_in,
                              void* d_out, int out_size)
{
    const float* x        = (const float*)d_in[0];
    const float* mesh_pos = (const float*)d_in[1];
    const int*   me32     = (const int*)  d_in[2];
    const float* ip_w1 = (const float*)d_in[4];
    const float* ip_b1 = (const float*)d_in[5];
    const float* ip_w2 = (const float*)d_in[6];
    const float* ip_b2 = (const float*)d_in[7];
    const float* ip_w3 = (const float*)d_in[8];
    const float* ip_b3 = (const float*)d_in[9];
    const float* bf    = (const float*)d_in[10];
    const float* mw1   = (const float*)d_in[11];
    const float* mb1   = (const float*)d_in[12];
    const float* mw2   = (const float*)d_in[13];
    const float* mb2   = (const float*)d_in[14];
    const float* mw3   = (const float*)d_in[15];
    const float* mb3   = (const float*)d_in[16];
    float* out = (float*)d_out;

    __half *h1p, *h2p, *hhp, *eaHp, *w2h, *w3h, *mw1h, *mw2h, *mw3h;
    float  *ebp;
    cudaGetSymbolAddress((void**)&h1p,  g_h1);
    cudaGetSymbolAddress((void**)&h2p,  g_h2a);
    cudaGetSymbolAddress((void**)&hhp,  g_hh);
    cudaGetSymbolAddress((void**)&eaHp, g_eaH);
    cudaGetSymbolAddress((void**)&ebp,  g_eb);
    cudaGetSymbolAddress((void**)&w2h,  g_w2h);
    cudaGetSymbolAddress((void**)&w3h,  g_w3h);
    cudaGetSymbolAddress((void**)&mw1h, g_mw1h);
    cudaGetSymbolAddress((void**)&mw2h, g_mw2h);
    cudaGetSymbolAddress((void**)&mw3h, g_mw3h);

    cudaFuncSetAttribute(gemm16<256,1,true >, cudaFuncAttributeMaxDynamicSharedMemorySize, GEMM_SMEM);
    cudaFuncSetAttribute(gemm16<256,2,true >, cudaFuncAttributeMaxDynamicSharedMemorySize, GEMM_SMEM);
    cudaFuncSetAttribute(gemm16<256,4,false>, cudaFuncAttributeMaxDynamicSharedMemorySize, GEMM_SMEM);
    cudaFuncSetAttribute(gemm16<256,0,true >, cudaFuncAttributeMaxDynamicSharedMemorySize, GEMM_SMEM);
    cudaFuncSetAttribute(edge_fused,          cudaFuncAttributeMaxDynamicSharedMemorySize, EDGE_SMEM);

    detect_kernel<<<1, 32>>>(me32);

    // single fp16 weight prep launch
    f2h_all<<<576, 256>>>(ip_w2, ip_w3, mw1, mw2, mw3, w2h, w3h, mw1h, mw2h, mw3h);

    // node encoder
    h1_kernel<<<N_NODES/64, 256>>>(x, ip_w1, ip_b1);
    gemm16<256,1,true ><<<dim3(N_NODES/128,2), 256, GEMM_SMEM>>>(
        h1p, 256, w2h, 256, ip_b2, h2p, 256, nullptr, nullptr);
    gemm16<256,2,true ><<<dim3(N_NODES/128,2), 256, GEMM_SMEM>>>(
        h2p, 256, w3h, 256, ip_b3, hhp, 256, mesh_pos, bf);

    // hoisted edge layer-1 halves: ea fp16 (no bias), eb fp32 (+b1)
    gemm16<256,4,false><<<dim3(N_NODES/128,4), 256, GEMM_SMEM>>>(
        hhp, 256, mw1h, 512, nullptr, eaHp, 512, nullptr, nullptr);
    gemm16<256,0,true ><<<dim3(N_DST/128,4), 256, GEMM_SMEM>>>(
        hhp, 256, mw1h + 256, 512, mb1, ebp, 512, nullptr, nullptr);

    // fused edge layers 2+3 + segment mean
    edge_fused<<<N_EDGES/64, 256, EDGE_SMEM>>>(
        eaHp, ebp, mw2h, mb2, mw3h, mb3, out, me32);
}

// round 9
// speedup vs baseline: 1.2393x; 1.0165x over previous
#include <cuda_runtime.h>
#include <cuda_fp16.h>
#include <math.h>
#include <stdint.h>

#define N_NODES 131072
#define N_DST   16384
#define DEG     16
#define N_EDGES (N_DST*DEG)
#define HID     256

// ---------------- global scratch (device globals: no runtime alloc) --------
__device__ __align__(16) __half g_h1 [(size_t)N_NODES * 256];
__device__ __align__(16) __half g_hh [(size_t)N_NODES * 256];
__device__ __align__(16) __half g_eaH[(size_t)N_NODES * 512];
__device__ __align__(16) float  g_eb [(size_t)N_DST   * 512];
__device__ __align__(16) __half g_w2h [256*256];
__device__ __align__(16) __half g_w3h [256*256];
__device__ __align__(16) __half g_mw1h[512*512];
__device__ __align__(16) __half g_mw2h[256*512];
__device__ __align__(16) __half g_mw3h[256*256];
__device__ int g_is64;

__device__ __forceinline__ float gelu_exact(float x){
    return 0.5f * x * (1.0f + erff(x * 0.70710678118654752f));
}
__device__ __forceinline__ uint32_t smem_u32(const void* p){
    uint32_t a;
    asm("{ .reg .u64 t; cvta.to.shared.u64 t, %1; cvt.u32.u64 %0, t; }" : "=r"(a) : "l"(p));
    return a;
}
__device__ __forceinline__ void mma16(float* c, const uint32_t* a, const uint32_t* b){
    asm volatile("mma.sync.aligned.m16n8k16.row.col.f32.f16.f16.f32 "
        "{%0,%1,%2,%3}, {%4,%5,%6,%7}, {%8,%9}, {%0,%1,%2,%3};"
        : "+f"(c[0]), "+f"(c[1]), "+f"(c[2]), "+f"(c[3])
        : "r"(a[0]), "r"(a[1]), "r"(a[2]), "r"(a[3]), "r"(b[0]), "r"(b[1]));
}
__device__ __forceinline__ void ldsm4(uint32_t& r0, uint32_t& r1, uint32_t& r2, uint32_t& r3,
                                      uint32_t addr){
    asm volatile("ldmatrix.sync.aligned.m8n8.x4.shared.b16 {%0,%1,%2,%3}, [%4];"
        : "=r"(r0), "=r"(r1), "=r"(r2), "=r"(r3) : "r"(addr));
}
#define CP16(dst, src) \
    asm volatile("cp.async.ca.shared.global [%0], [%1], 16;" :: "r"(dst), "l"(src) : "memory")
#define CP_COMMIT() asm volatile("cp.async.commit_group;" ::: "memory")
#define CP_WAIT2()  asm volatile("cp.async.wait_group 2;"  ::: "memory")
#define CP_WAIT1()  asm volatile("cp.async.wait_group 1;"  ::: "memory")

// ---------------------------------------------------------------------------
__global__ void detect_kernel(const int* __restrict__ me32){
    if (threadIdx.x == 0 && blockIdx.x == 0) g_is64 = (me32[32] != 1) ? 1 : 0;
}

// one-shot fp16 conversion of all five weight matrices (float4 granularity)
__global__ __launch_bounds__(256)
void f2h_all(const float* __restrict__ w2, const float* __restrict__ w3,
             const float* __restrict__ m1, const float* __restrict__ m2,
             const float* __restrict__ m3,
             __half* __restrict__ dw2, __half* __restrict__ dw3,
             __half* __restrict__ dm1, __half* __restrict__ dm2,
             __half* __restrict__ dm3)
{
    int i = blockIdx.x*256 + threadIdx.x;          // float4 index, total 147456
    const float* s; __half* d; int off;
    if      (i <  16384){ s = w2; d = dw2; off = i; }
    else if (i <  32768){ s = w3; d = dw3; off = i - 16384; }
    else if (i <  98304){ s = m1; d = dm1; off = i - 32768; }
    else if (i < 131072){ s = m2; d = dm2; off = i - 98304; }
    else                { s = m3; d = dm3; off = i - 131072; }
    float4 v = ((const float4*)s)[off];
    __half2 h0 = __floats2half2_rn(v.x, v.y), h1 = __floats2half2_rn(v.z, v.w);
    uint2 pk;
    pk.x = *reinterpret_cast<uint32_t*>(&h0);
    pk.y = *reinterpret_cast<uint32_t*>(&h1);
    ((uint2*)d)[off] = pk;
}

// h1 = gelu(x @ W1^T + b1), K=3: fp32 math, fp16 store.
__global__ __launch_bounds__(256)
void h1_kernel(const float* __restrict__ x,
               const float* __restrict__ w1, const float* __restrict__ b1){
    __shared__ float sx[64*3];
    const int t  = threadIdx.x;
    const int n0 = blockIdx.x * 64;
    for (int i = t; i < 64*3; i += 256) sx[i] = x[(size_t)n0*3 + i];
    __syncthreads();
    const float wa = w1[t*3+0], wb = w1[t*3+1], wc = w1[t*3+2], bb = b1[t];
    for (int n = 0; n < 64; n++){
        float v = fmaf(wa, sx[n*3+0], fmaf(wb, sx[n*3+1], fmaf(wc, sx[n*3+2], bb)));
        g_h1[(size_t)(n0+n)*256 + t] = __float2half_rn(gelu_exact(v));
    }
}

// ---------------------------------------------------------------------------
// fp16 mma.sync GEMM: C[M x Ntot] = epi(A[M x K] @ W[Ntot x K]^T + bias)
// Block 128x128, BK=32, 256 threads = 8 warps (4m x 2n), warp tile 32x64.
// 4-stage cp.async, 64KB smem, 2 CTAs/SM.
// EPI: 0=fp32 store(+bias), 4=plain fp16.
// ---------------------------------------------------------------------------
#define GEMM_SMEM (64*1024)

template<int K, int EPI, bool HAS_BIAS>
__global__ __launch_bounds__(256, 2)
void gemm16(const __half* __restrict__ A, int lda,
            const __half* __restrict__ W, int ldw,
            const float* __restrict__ bias,
            void* __restrict__ Cout, int ldc)
{
    extern __shared__ char smem[];
    const int t    = threadIdx.x;
    const int lane = t & 31;
    const int w    = t >> 5;
    const int wm   = w >> 1, wn = w & 1;          // 4 x 2 warp grid
    const int gid  = lane >> 2, tig = lane & 3;
    const int m0   = blockIdx.x * 128;
    const int n0   = blockIdx.y * 128;
    const uint32_t sb = smem_u32(smem);

    // per-lane ldmatrix base offsets (k-slice s=0 baked in; s=1 -> XOR 0x20)
    uint32_t offA[2], offB[4];
    {
        const int l8 = lane & 7;
        const int h3 = (lane >> 3) & 1;
        const int h4 = lane >> 4;
        #pragma unroll
        for (int mi = 0; mi < 2; mi++){
            int rA = wm*32 + mi*16 + h3*8 + l8;
            int sw = (rA >> 1) & 3;
            offA[mi] = (uint32_t)(rA*64) + (uint32_t)((h4 ^ sw) << 4);
        }
        #pragma unroll
        for (int p = 0; p < 4; p++){
            int rB = wn*64 + p*16 + h4*8 + l8;
            int sw = (rB >> 1) & 3;
            offB[p] = (uint32_t)(rB*64) + (uint32_t)((h3 ^ sw) << 4);
        }
    }

    float acc[2][8][4];
    #pragma unroll
    for (int i = 0; i < 2; i++)
        #pragma unroll
        for (int j = 0; j < 8; j++)
            #pragma unroll
            for (int r = 0; r < 4; r++) acc[i][j][r] = 0.f;

    constexpr int NC = K / 32;

    auto produce = [&](int kc){
        const int st = kc & 3;
        #pragma unroll
        for (int it = 0; it < 2; it++){
            const int idx = it*256 + t, r = idx >> 2, c = idx & 3;
            uint32_t dst = sb + st*8192 + r*64 + (uint32_t)((c ^ ((r>>1)&3)) << 4);
            CP16(dst, (const void*)(A + (size_t)(m0 + r)*lda + kc*32 + c*8));
        }
        #pragma unroll
        for (int it = 0; it < 2; it++){
            const int idx = it*256 + t, rr = idx >> 2, cc = idx & 3;
            uint32_t db = sb + 32768 + st*8192 + rr*64 + (uint32_t)((cc ^ ((rr>>1)&3)) << 4);
            CP16(db, (const void*)(W + (size_t)(n0 + rr)*ldw + kc*32 + cc*8));
        }
        CP_COMMIT();
    };

    produce(0); produce(1); produce(2);

    #pragma unroll 1
    for (int kc = 0; kc < NC; kc++){
        CP_WAIT2();
        __syncthreads();
        const uint32_t aB = sb + (kc & 3)*8192;
        const uint32_t bB = sb + 32768u + (kc & 3)*8192;
        #pragma unroll
        for (int s = 0; s < 2; s++){
            const uint32_t sx = (uint32_t)s << 5;
            uint32_t afr[2][4], bfr[8][2];
            #pragma unroll
            for (int mi = 0; mi < 2; mi++)
                ldsm4(afr[mi][0], afr[mi][1], afr[mi][2], afr[mi][3],
                      aB + (offA[mi] ^ sx));
            #pragma unroll
            for (int p = 0; p < 4; p++)
                ldsm4(bfr[2*p][0], bfr[2*p][1], bfr[2*p+1][0], bfr[2*p+1][1],
                      bB + (offB[p] ^ sx));
            #pragma unroll
            for (int mi = 0; mi < 2; mi++)
                #pragma unroll
                for (int nj = 0; nj < 8; nj++)
                    mma16(acc[mi][nj], afr[mi], bfr[nj]);
        }
        if (kc + 3 < NC) produce(kc + 3); else CP_COMMIT();
    }

    // ---- epilogue ----
    #pragma unroll
    for (int mi = 0; mi < 2; mi++){
        const int r0 = m0 + wm*32 + mi*16 + gid;
        const int r1 = r0 + 8;
        #pragma unroll
        for (int nj = 0; nj < 8; nj++){
            const int cb = n0 + wn*64 + nj*8 + 2*tig;
            float v0 = acc[mi][nj][0], v1 = acc[mi][nj][1];
            float v2 = acc[mi][nj][2], v3 = acc[mi][nj][3];
            if (HAS_BIAS){
                const float b0 = bias[cb], b1 = bias[cb+1];
                v0 += b0; v1 += b1; v2 += b0; v3 += b1;
            }
            if (EPI == 0){
                float* C = (float*)Cout;
                *(float2*)(C + (size_t)r0*ldc + cb) = make_float2(v0, v1);
                *(float2*)(C + (size_t)r1*ldc + cb) = make_float2(v2, v3);
            } else {
                __half* C = (__half*)Cout;
                *(__half2*)(C + (size_t)r0*ldc + cb) = __floats2half2_rn(v0, v1);
                *(__half2*)(C + (size_t)r1*ldc + cb) = __floats2half2_rn(v2, v3);
            }
        }
    }
}

// ---------------------------------------------------------------------------
// Fused node-encoder kernel, 2 CTAs/SM: per block of 64 nodes:
//   phase 1: h2 = gelu(h1 @ W2^T + b2)            (K=256)  -> SMEM
//   phase 2: hh = h2 @ W3^T + b3 + fourier(pos)   (K=256)  -> gmem fp16
// SMEM 64KB: ph1: W2 3x16KB at [0,48K), A(h1) 3x4KB at [48K,60K);
//            ph2: h2 64x512B at [0,32K), W3 2x16KB at [32K,64K).
// ---------------------------------------------------------------------------
#define FUSED_SMEM (64*1024)

__global__ __launch_bounds__(256, 2)
void node_fused(const __half* __restrict__ h1g,
                const __half* __restrict__ W2, const float* __restrict__ b2,
                const __half* __restrict__ W3, const float* __restrict__ b3,
                const float* __restrict__ pos, const float* __restrict__ bfour,
                __half* __restrict__ hh)
{
    extern __shared__ char smem[];
    const int t    = threadIdx.x;
    const int lane = t & 31;
    const int w    = t >> 5;
    const int wm   = w >> 2, wn = w & 3;          // 2 x 4 warp grid
    const int gid  = lane >> 2, tig = lane & 3;
    const int m0   = blockIdx.x * 64;
    const uint32_t sb = smem_u32(smem);

    // per-lane ldmatrix offsets
    uint32_t offA[2], offB[4], baseM[2];
    int swM[2];
    const int l8 = lane & 7;
    const int h3 = (lane >> 3) & 1;
    const int h4 = lane >> 4;
    #pragma unroll
    for (int mi = 0; mi < 2; mi++){
        int rA = wm*32 + mi*16 + h3*8 + l8;          // 0..63
        int sw = (rA >> 1) & 3;
        offA[mi] = (uint32_t)(rA*64) + (uint32_t)((h4 ^ sw) << 4);
        baseM[mi] = (uint32_t)(rA*512);
        swM[mi] = rA & 7;
    }
    #pragma unroll
    for (int p = 0; p < 4; p++){
        int rB = wn*64 + p*16 + h4*8 + l8;           // 0..255
        int sw = (rB >> 1) & 3;
        offB[p] = (uint32_t)(rB*64) + (uint32_t)((h3 ^ sw) << 4);
    }

    float acc[2][8][4];
    #pragma unroll
    for (int i = 0; i < 2; i++)
        #pragma unroll
        for (int j = 0; j < 8; j++)
            #pragma unroll
            for (int r = 0; r < 4; r++) acc[i][j][r] = 0.f;

    // ---- phase 1 producer: A = h1 rows (cp.async), B = W2 (cp.async)
    auto produce1 = [&](int kc, int st){
        const int r = t >> 2, c = t & 3;             // r: 0..63
        uint32_t da = sb + 49152 + st*4096 + r*64 + (uint32_t)((c ^ ((r>>1)&3)) << 4);
        CP16(da, (const void*)(h1g + (size_t)(m0 + r)*256 + kc*32 + c*8));
        #pragma unroll
        for (int it = 0; it < 4; it++){
            const int idx = it*256 + t, rr = idx >> 2, cc = idx & 3;
            uint32_t db = sb + st*16384 + rr*64 + (uint32_t)((cc ^ ((rr>>1)&3)) << 4);
            CP16(db, (const void*)(W2 + (size_t)rr*256 + kc*32 + cc*8));
        }
        CP_COMMIT();
    };

    produce1(0, 0); produce1(1, 1);

    int ccur = 0, pcur = 2;
    #pragma unroll 1
    for (int kc = 0; kc < 8; kc++){
        CP_WAIT1();
        __syncthreads();
        const uint32_t aB = sb + 49152u + ccur*4096;
        const uint32_t bB = sb + ccur*16384;
        #pragma unroll
        for (int s = 0; s < 2; s++){
            const uint32_t sx = (uint32_t)s << 5;
            uint32_t afr[2][4], bfr[8][2];
            #pragma unroll
            for (int mi = 0; mi < 2; mi++)
                ldsm4(afr[mi][0], afr[mi][1], afr[mi][2], afr[mi][3],
                      aB + (offA[mi] ^ sx));
            #pragma unroll
            for (int p = 0; p < 4; p++)
                ldsm4(bfr[2*p][0], bfr[2*p][1], bfr[2*p+1][0], bfr[2*p+1][1],
                      bB + (offB[p] ^ sx));
            #pragma unroll
            for (int mi = 0; mi < 2; mi++)
                #pragma unroll
                for (int nj = 0; nj < 8; nj++)
                    mma16(acc[mi][nj], afr[mi], bfr[nj]);
        }
        if (kc + 2 < 8) produce1(kc + 2, pcur); else CP_COMMIT();
        ccur = (ccur == 2) ? 0 : ccur + 1;
        pcur = (pcur == 2) ? 0 : pcur + 1;
    }

    __syncthreads();   // everyone done reading phase-1 tiles

    // ---- phase 2 W3 producer into [32K,64K), 2 stages
    auto produce2 = [&](int kc){
        const int st = kc & 1;
        #pragma unroll
        for (int it = 0; it < 4; it++){
            const int idx = it*256 + t, rr = idx >> 2, cc = idx & 3;
            uint32_t db = sb + 32768 + st*16384 + rr*64 + (uint32_t)((cc ^ ((rr>>1)&3)) << 4);
            CP16(db, (const void*)(W3 + (size_t)rr*256 + kc*32 + cc*8));
        }
        CP_COMMIT();
    };
    produce2(0);

    // ---- epilogue-1: h2 = gelu(acc + b2) -> fp16 SMEM at [0, 32K)
    #pragma unroll
    for (int mi = 0; mi < 2; mi++){
        const int lr0 = wm*32 + mi*16 + gid;
        const int lr1 = lr0 + 8;
        #pragma unroll
        for (int nj = 0; nj < 8; nj++){
            const int cb = wn*64 + nj*8 + 2*tig;
            const float b0 = b2[cb], b1 = b2[cb+1];
            __half2 lo = __floats2half2_rn(gelu_exact(acc[mi][nj][0] + b0),
                                           gelu_exact(acc[mi][nj][1] + b1));
            __half2 hi = __floats2half2_rn(gelu_exact(acc[mi][nj][2] + b0),
                                           gelu_exact(acc[mi][nj][3] + b1));
            const int blk = cb >> 3;
            *(__half2*)(smem + lr0*512 + ((blk ^ (lr0 & 7)) << 4) + 4*tig) = lo;
            *(__half2*)(smem + lr1*512 + ((blk ^ (lr1 & 7)) << 4) + 4*tig) = hi;
            acc[mi][nj][0] = 0.f; acc[mi][nj][1] = 0.f;
            acc[mi][nj][2] = 0.f; acc[mi][nj][3] = 0.f;
        }
    }

    // ---- phase 2 main loop (K=256, 8 chunks)
    #pragma unroll 1
    for (int kc = 0; kc < 8; kc++){
        __syncthreads();                 // prev compute done; h2 visible (kc=0)
        if (kc + 1 < 8) produce2(kc + 1); else CP_COMMIT();
        CP_WAIT1();
        __syncthreads();
        const uint32_t bB = sb + 32768u + (kc & 1)*16384;
        #pragma unroll
        for (int s = 0; s < 2; s++){
            const uint32_t sx = (uint32_t)s << 5;
            uint32_t afr[2][4], bfr[8][2];
            #pragma unroll
            for (int mi = 0; mi < 2; mi++){
                const int blk = kc*4 + h4;
                const uint32_t offM = (uint32_t)((blk ^ swM[mi]) << 4);
                ldsm4(afr[mi][0], afr[mi][1], afr[mi][2], afr[mi][3],
                      sb + baseM[mi] + (offM ^ sx));
            }
            #pragma unroll
            for (int p = 0; p < 4; p++)
                ldsm4(bfr[2*p][0], bfr[2*p][1], bfr[2*p+1][0], bfr[2*p+1][1],
                      bB + (offB[p] ^ sx));
            #pragma unroll
            for (int mi = 0; mi < 2; mi++)
                #pragma unroll
                for (int nj = 0; nj < 8; nj++)
                    mma16(acc[mi][nj], afr[mi], bfr[nj]);
        }
    }

    // ---- final epilogue: hh = acc + b3 + fourier -> fp16 gmem
    #pragma unroll
    for (int mi = 0; mi < 2; mi++){
        const int r0 = m0 + wm*32 + mi*16 + gid;
        const int r1 = r0 + 8;
        const float p00 = pos[(size_t)r0*2], p01 = pos[(size_t)r0*2 + 1];
        const float p10 = pos[(size_t)r1*2], p11 = pos[(size_t)r1*2 + 1];
        #pragma unroll
        for (int nj = 0; nj < 8; nj++){
            const int cb = wn*64 + nj*8 + 2*tig;
            const float b0 = b3[cb], b1 = b3[cb+1];
            float v0 = acc[mi][nj][0] + b0, v1 = acc[mi][nj][1] + b1;
            float v2 = acc[mi][nj][2] + b0, v3 = acc[mi][nj][3] + b1;
            const int o0 = cb, o1 = cb + 1;
            const float ba0 = bfour[(o0 & 127)*2], bb0 = bfour[(o0 & 127)*2 + 1];
            const float ba1 = bfour[(o1 & 127)*2], bb1 = bfour[(o1 & 127)*2 + 1];
            const float TP = 6.283185307179586f;
            float pl0 = TP*(p00*ba0 + p01*bb0), pl1 = TP*(p00*ba1 + p01*bb1);
            float ph0 = TP*(p10*ba0 + p11*bb0), ph1 = TP*(p10*ba1 + p11*bb1);
            v0 += (o0 < 128) ? __cosf(pl0) : __sinf(pl0);
            v1 += (o1 < 128) ? __cosf(pl1) : __sinf(pl1);
            v2 += (o0 < 128) ? __cosf(ph0) : __sinf(ph0);
            v3 += (o1 < 128) ? __cosf(ph1) : __sinf(ph1);
            *(__half2*)(hh + (size_t)r0*256 + cb) = __floats2half2_rn(v0, v1);
            *(__half2*)(hh + (size_t)r1*256 + cb) = __floats2half2_rn(v2, v3);
        }
    }
}

// ---------------------------------------------------------------------------
// Fused edge kernel, 2 CTAs/SM: per block of 64 edges (= 4 dsts):
//   phase 1: m2 = gelu([gelu(ea[src]+eb[dst])] @ W2^T + b2)  (K=512)  -> SMEM
//   phase 2: m3 = m2 @ W3^T + b3 ; out[dst] = mean_16(m3)    (K=256)
// ---------------------------------------------------------------------------
#define EDGE_SMEM (64*1024)

__global__ __launch_bounds__(256, 2)
void edge_fused(const __half* __restrict__ eaH, const float* __restrict__ ebF,
                const __half* __restrict__ W2, const float* __restrict__ b2,
                const __half* __restrict__ W3, const float* __restrict__ b3,
                float* __restrict__ out, const int* __restrict__ me32)
{
    extern __shared__ char smem[];
    __shared__ int sSrc[64], sDst[64];
    const int t    = threadIdx.x;
    const int lane = t & 31;
    const int w    = t >> 5;
    const int wm   = w >> 2, wn = w & 3;          // 2 x 4 warp grid
    const int gid  = lane >> 2, tig = lane & 3;
    const int m0   = blockIdx.x * 64;
    const uint32_t sb = smem_u32(smem);

    if (t < 64){
        const int e = m0 + t; int s, d;
        if (g_is64){ d = me32[4*e]; s = me32[4*e+2]; }
        else       { d = me32[2*e]; s = me32[2*e+1]; }
        sSrc[t] = s; sDst[t] = d;
    }
    __syncthreads();

    // per-lane ldmatrix offsets
    uint32_t offA[2], offB[4], baseM[2];
    int swM[2];
    const int l8 = lane & 7;
    const int h3 = (lane >> 3) & 1;
    const int h4 = lane >> 4;
    #pragma unroll
    for (int mi = 0; mi < 2; mi++){
        int rA = wm*32 + mi*16 + h3*8 + l8;          // 0..63
        int sw = (rA >> 1) & 3;
        offA[mi] = (uint32_t)(rA*64) + (uint32_t)((h4 ^ sw) << 4);
        baseM[mi] = (uint32_t)(rA*512);
        swM[mi] = rA & 7;
    }
    #pragma unroll
    for (int p = 0; p < 4; p++){
        int rB = wn*64 + p*16 + h4*8 + l8;           // 0..255
        int sw = (rB >> 1) & 3;
        offB[p] = (uint32_t)(rB*64) + (uint32_t)((h3 ^ sw) << 4);
    }

    float acc[2][8][4];
    #pragma unroll
    for (int i = 0; i < 2; i++)
        #pragma unroll
        for (int j = 0; j < 8; j++)
            #pragma unroll
            for (int r = 0; r < 4; r++) acc[i][j][r] = 0.f;

    // ---- phase 1 producer: A = gelu(ea[src]+eb[dst]) (STS), B = W2 (cp.async)
    auto produce1 = [&](int kc, int st){
        const int r = t >> 2, c = t & 3;             // r: 0..63
        const int k0 = kc*32 + c*8;
        uint4 av = *(const uint4*)(eaH + (size_t)sSrc[r]*512 + k0);
        const float* pb = ebF + (size_t)sDst[r]*512 + k0;
        float4 e0 = *(const float4*)pb, e1 = *(const float4*)(pb + 4);
        const __half2* ah = (const __half2*)&av;
        float2 f0 = __half22float2(ah[0]), f1 = __half22float2(ah[1]);
        float2 f2 = __half22float2(ah[2]), f3 = __half22float2(ah[3]);
        __half2 h0 = __floats2half2_rn(gelu_exact(f0.x+e0.x), gelu_exact(f0.y+e0.y));
        __half2 h1 = __floats2half2_rn(gelu_exact(f1.x+e0.z), gelu_exact(f1.y+e0.w));
        __half2 h2 = __floats2half2_rn(gelu_exact(f2.x+e1.x), gelu_exact(f2.y+e1.y));
        __half2 h3v = __floats2half2_rn(gelu_exact(f3.x+e1.z), gelu_exact(f3.y+e1.w));
        uint4 pk;
        pk.x = *reinterpret_cast<uint32_t*>(&h0);
        pk.y = *reinterpret_cast<uint32_t*>(&h1);
        pk.z = *reinterpret_cast<uint32_t*>(&h2);
        pk.w = *reinterpret_cast<uint32_t*>(&h3v);
        *(uint4*)(smem + 49152 + st*4096 + r*64 + ((c ^ ((r>>1)&3)) << 4)) = pk;
        #pragma unroll
        for (int it = 0; it < 4; it++){
            const int idx = it*256 + t, rr = idx >> 2, cc = idx & 3;
            uint32_t db = sb + st*16384 + rr*64 + (uint32_t)((cc ^ ((rr>>1)&3)) << 4);
            CP16(db, (const void*)(W2 + (size_t)rr*512 + kc*32 + cc*8));
        }
        CP_COMMIT();
    };

    produce1(0, 0); produce1(1, 1);

    int ccur = 0, pcur = 2;
    #pragma unroll 1
    for (int kc = 0; kc < 16; kc++){
        CP_WAIT1();
        __syncthreads();
        const uint32_t aB = sb + 49152u + ccur*4096;
        const uint32_t bB = sb + ccur*16384;
        #pragma unroll
        for (int s = 0; s < 2; s++){
            const uint32_t sx = (uint32_t)s << 5;
            uint32_t afr[2][4], bfr[8][2];
            #pragma unroll
            for (int mi = 0; mi < 2; mi++)
                ldsm4(afr[mi][0], afr[mi][1], afr[mi][2], afr[mi][3],
                      aB + (offA[mi] ^ sx));
            #pragma unroll
            for (int p = 0; p < 4; p++)
                ldsm4(bfr[2*p][0], bfr[2*p][1], bfr[2*p+1][0], bfr[2*p+1][1],
                      bB + (offB[p] ^ sx));
            #pragma unroll
            for (int mi = 0; mi < 2; mi++)
                #pragma unroll
                for (int nj = 0; nj < 8; nj++)
                    mma16(acc[mi][nj], afr[mi], bfr[nj]);
        }
        if (kc + 2 < 16) produce1(kc + 2, pcur); else CP_COMMIT();
        ccur = (ccur == 2) ? 0 : ccur + 1;
        pcur = (pcur == 2) ? 0 : pcur + 1;
    }

    __syncthreads();   // everyone done reading phase-1 tiles

    // ---- phase 2 W3 producer into [32K,64K), 2 stages
    auto produce2 = [&](int kc){
        const int st = kc & 1;
        #pragma unroll
        for (int it = 0; it < 4; it++){
            const int idx = it*256 + t, rr = idx >> 2, cc = idx & 3;
            uint32_t db = sb + 32768 + st*16384 + rr*64 + (uint32_t)((cc ^ ((rr>>1)&3)) << 4);
            CP16(db, (const void*)(W3 + (size_t)rr*256 + kc*32 + cc*8));
        }
        CP_COMMIT();
    };
    produce2(0);

    // ---- epilogue-1: m2 = gelu(acc + b2) -> fp16 SMEM at [0, 32K)
    #pragma unroll
    for (int mi = 0; mi < 2; mi++){
        const int lr0 = wm*32 + mi*16 + gid;
        const int lr1 = lr0 + 8;
        #pragma unroll
        for (int nj = 0; nj < 8; nj++){
            const int cb = wn*64 + nj*8 + 2*tig;
            const float b0 = b2[cb], b1 = b2[cb+1];
            __half2 lo = __floats2half2_rn(gelu_exact(acc[mi][nj][0] + b0),
                                           gelu_exact(acc[mi][nj][1] + b1));
            __half2 hi = __floats2half2_rn(gelu_exact(acc[mi][nj][2] + b0),
                                           gelu_exact(acc[mi][nj][3] + b1));
            const int blk = cb >> 3;
            *(__half2*)(smem + lr0*512 + ((blk ^ (lr0 & 7)) << 4) + 4*tig) = lo;
            *(__half2*)(smem + lr1*512 + ((blk ^ (lr1 & 7)) << 4) + 4*tig) = hi;
            acc[mi][nj][0] = 0.f; acc[mi][nj][1] = 0.f;
            acc[mi][nj][2] = 0.f; acc[mi][nj][3] = 0.f;
        }
    }

    // ---- phase 2 main loop (K=256, 8 chunks)
    #pragma unroll 1
    for (int kc = 0; kc < 8; kc++){
        __syncthreads();                 // prev compute done; m2 visible (kc=0)
        if (kc + 1 < 8) produce2(kc + 1); else CP_COMMIT();
        CP_WAIT1();
        __syncthreads();
        const uint32_t bB = sb + 32768u + (kc & 1)*16384;
        #pragma unroll
        for (int s = 0; s < 2; s++){
            const uint32_t sx = (uint32_t)s << 5;
            uint32_t afr[2][4], bfr[8][2];
            #pragma unroll
            for (int mi = 0; mi < 2; mi++){
                const int blk = kc*4 + h4;
                const uint32_t offM = (uint32_t)((blk ^ swM[mi]) << 4);
                ldsm4(afr[mi][0], afr[mi][1], afr[mi][2], afr[mi][3],
                      sb + baseM[mi] + (offM ^ sx));
            }
            #pragma unroll
            for (int p = 0; p < 4; p++)
                ldsm4(bfr[2*p][0], bfr[2*p][1], bfr[2*p+1][0], bfr[2*p+1][1],
                      bB + (offB[p] ^ sx));
            #pragma unroll
            for (int mi = 0; mi < 2; mi++)
                #pragma unroll
                for (int nj = 0; nj < 8; nj++)
                    mma16(acc[mi][nj], afr[mi], bfr[nj]);
        }
    }

    // ---- final epilogue: segment mean over 16 edges + b3
    #pragma unroll
    for (int mi = 0; mi < 2; mi++){
        #pragma unroll
        for (int nj = 0; nj < 8; nj++){
            const int cb = wn*64 + nj*8 + 2*tig;
            float s0 = acc[mi][nj][0] + acc[mi][nj][2];
            float s1 = acc[mi][nj][1] + acc[mi][nj][3];
            s0 += __shfl_xor_sync(0xffffffffu, s0, 4);
            s0 += __shfl_xor_sync(0xffffffffu, s0, 8);
            s0 += __shfl_xor_sync(0xffffffffu, s0, 16);
            s1 += __shfl_xor_sync(0xffffffffu, s1, 4);
            s1 += __shfl_xor_sync(0xffffffffu, s1, 8);
            s1 += __shfl_xor_sync(0xffffffffu, s1, 16);
            if (lane < 4){
                const int dst = (m0 + wm*32 + mi*16) >> 4;
                float2 o;
                o.x = s0 * 0.0625f + b3[cb];
                o.y = s1 * 0.0625f + b3[cb+1];
                *(float2*)(out + (size_t)dst*256 + cb) = o;
            }
        }
    }
}

// ---------------------------------------------------------------------------
extern "C" void kernel_launch(void* const* d_in, const int* in_sizes, int n_in,
                              void* d_out, int out_size)
{
    const float* x        = (const float*)d_in[0];
    const float* mesh_pos = (const float*)d_in[1];
    const int*   me32     = (const int*)  d_in[2];
    const float* ip_w1 = (const float*)d_in[4];
    const float* ip_b1 = (const float*)d_in[5];
    const float* ip_w2 = (const float*)d_in[6];
    const float* ip_b2 = (const float*)d_in[7];
    const float* ip_w3 = (const float*)d_in[8];
    const float* ip_b3 = (const float*)d_in[9];
    const float* bf    = (const float*)d_in[10];
    const float* mw1   = (const float*)d_in[11];
    const float* mb1   = (const float*)d_in[12];
    const float* mw2   = (const float*)d_in[13];
    const float* mb2   = (const float*)d_in[14];
    const float* mw3   = (const float*)d_in[15];
    const float* mb3   = (const float*)d_in[16];
    float* out = (float*)d_out;

    __half *h1p, *hhp, *eaHp, *w2h, *w3h, *mw1h, *mw2h, *mw3h;
    float  *ebp;
    cudaGetSymbolAddress((void**)&h1p,  g_h1);
    cudaGetSymbolAddress((void**)&hhp,  g_hh);
    cudaGetSymbolAddress((void**)&eaHp, g_eaH);
    cudaGetSymbolAddress((void**)&ebp,  g_eb);
    cudaGetSymbolAddress((void**)&w2h,  g_w2h);
    cudaGetSymbolAddress((void**)&w3h,  g_w3h);
    cudaGetSymbolAddress((void**)&mw1h, g_mw1h);
    cudaGetSymbolAddress((void**)&mw2h, g_mw2h);
    cudaGetSymbolAddress((void**)&mw3h, g_mw3h);

    cudaFuncSetAttribute(gemm16<256,4,false>, cudaFuncAttributeMaxDynamicSharedMemorySize, GEMM_SMEM);
    cudaFuncSetAttribute(gemm16<256,0,true >, cudaFuncAttributeMaxDynamicSharedMemorySize, GEMM_SMEM);
    cudaFuncSetAttribute(node_fused,          cudaFuncAttributeMaxDynamicSharedMemorySize, FUSED_SMEM);
    cudaFuncSetAttribute(edge_fused,          cudaFuncAttributeMaxDynamicSharedMemorySize, EDGE_SMEM);

    detect_kernel<<<1, 32>>>(me32);

    // single fp16 weight prep launch
    f2h_all<<<576, 256>>>(ip_w2, ip_w3, mw1, mw2, mw3, w2h, w3h, mw1h, mw2h, mw3h);

    // node encoder: h1, then fused layers 2+3 (+fourier) -> hh
    h1_kernel<<<N_NODES/64, 256>>>(x, ip_w1, ip_b1);
    node_fused<<<N_NODES/64, 256, FUSED_SMEM>>>(
        h1p, w2h, ip_b2, w3h, ip_b3, mesh_pos, bf, hhp);

    // hoisted edge layer-1 halves: ea fp16 (no bias), eb fp32 (+b1)
    gemm16<256,4,false><<<dim3(N_NODES/128,4), 256, GEMM_SMEM>>>(
        hhp, 256, mw1h, 512, nullptr, eaHp, 512);
    gemm16<256,0,true ><<<dim3(N_DST/128,4), 256, GEMM_SMEM>>>(
        hhp, 256, mw1h + 256, 512, mb1, ebp, 512);

    // fused edge layers 2+3 + segment mean
    edge_fused<<<N_EDGES/64, 256, EDGE_SMEM>>>(
        eaHp, ebp, mw2h, mb2, mw3h, mb3, out, me32);
}

// round 10
// speedup vs baseline: 1.4012x; 1.1306x over previous
#include <cuda_runtime.h>
#include <cuda_fp16.h>
#include <math.h>
#include <stdint.h>

#define N_NODES 131072
#define N_DST   16384
#define DEG     16
#define N_EDGES (N_DST*DEG)
#define HID     256

// ---------------- global scratch (device globals: no runtime alloc) --------
__device__ __align__(16) __half g_h1 [(size_t)N_NODES * 256];   // h1, later m2mean
__device__ __align__(16) __half g_hh [(size_t)N_NODES * 256];
__device__ __align__(16) __half g_eaH[(size_t)N_NODES * 512];
__device__ __align__(16) float  g_eb [(size_t)N_DST   * 512];
__device__ __align__(16) __half g_w2h [256*256];
__device__ __align__(16) __half g_w3h [256*256];
__device__ __align__(16) __half g_mw1h[512*512];
__device__ __align__(16) __half g_mw2h[256*512];
__device__ __align__(16) __half g_mw3h[256*256];
__device__ int g_is64;

__device__ __forceinline__ float gelu_exact(float x){
    return 0.5f * x * (1.0f + erff(x * 0.70710678118654752f));
}
__device__ __forceinline__ uint32_t smem_u32(const void* p){
    uint32_t a;
    asm("{ .reg .u64 t; cvta.to.shared.u64 t, %1; cvt.u32.u64 %0, t; }" : "=r"(a) : "l"(p));
    return a;
}
__device__ __forceinline__ void mma16(float* c, const uint32_t* a, const uint32_t* b){
    asm volatile("mma.sync.aligned.m16n8k16.row.col.f32.f16.f16.f32 "
        "{%0,%1,%2,%3}, {%4,%5,%6,%7}, {%8,%9}, {%0,%1,%2,%3};"
        : "+f"(c[0]), "+f"(c[1]), "+f"(c[2]), "+f"(c[3])
        : "r"(a[0]), "r"(a[1]), "r"(a[2]), "r"(a[3]), "r"(b[0]), "r"(b[1]));
}
__device__ __forceinline__ void ldsm4(uint32_t& r0, uint32_t& r1, uint32_t& r2, uint32_t& r3,
                                      uint32_t addr){
    asm volatile("ldmatrix.sync.aligned.m8n8.x4.shared.b16 {%0,%1,%2,%3}, [%4];"
        : "=r"(r0), "=r"(r1), "=r"(r2), "=r"(r3) : "r"(addr));
}
#define CP16(dst, src) \
    asm volatile("cp.async.ca.shared.global [%0], [%1], 16;" :: "r"(dst), "l"(src) : "memory")
#define CP_COMMIT() asm volatile("cp.async.commit_group;" ::: "memory")
#define CP_WAIT2()  asm volatile("cp.async.wait_group 2;"  ::: "memory")
#define CP_WAIT1()  asm volatile("cp.async.wait_group 1;"  ::: "memory")

// ---------------------------------------------------------------------------
__global__ void detect_kernel(const int* __restrict__ me32){
    if (threadIdx.x == 0 && blockIdx.x == 0) g_is64 = (me32[32] != 1) ? 1 : 0;
}

// one-shot fp16 conversion of all five weight matrices (float4 granularity)
__global__ __launch_bounds__(256)
void f2h_all(const float* __restrict__ w2, const float* __restrict__ w3,
             const float* __restrict__ m1, const float* __restrict__ m2,
             const float* __restrict__ m3,
             __half* __restrict__ dw2, __half* __restrict__ dw3,
             __half* __restrict__ dm1, __half* __restrict__ dm2,
             __half* __restrict__ dm3)
{
    int i = blockIdx.x*256 + threadIdx.x;          // float4 index, total 147456
    const float* s; __half* d; int off;
    if      (i <  16384){ s = w2; d = dw2; off = i; }
    else if (i <  32768){ s = w3; d = dw3; off = i - 16384; }
    else if (i <  98304){ s = m1; d = dm1; off = i - 32768; }
    else if (i < 131072){ s = m2; d = dm2; off = i - 98304; }
    else                { s = m3; d = dm3; off = i - 131072; }
    float4 v = ((const float4*)s)[off];
    __half2 h0 = __floats2half2_rn(v.x, v.y), h1 = __floats2half2_rn(v.z, v.w);
    uint2 pk;
    pk.x = *reinterpret_cast<uint32_t*>(&h0);
    pk.y = *reinterpret_cast<uint32_t*>(&h1);
    ((uint2*)d)[off] = pk;
}

// h1 = gelu(x @ W1^T + b1), K=3: fp32 math, fp16 store.
__global__ __launch_bounds__(256)
void h1_kernel(const float* __restrict__ x,
               const float* __restrict__ w1, const float* __restrict__ b1){
    __shared__ float sx[64*3];
    const int t  = threadIdx.x;
    const int n0 = blockIdx.x * 64;
    for (int i = t; i < 64*3; i += 256) sx[i] = x[(size_t)n0*3 + i];
    __syncthreads();
    const float wa = w1[t*3+0], wb = w1[t*3+1], wc = w1[t*3+2], bb = b1[t];
    for (int n = 0; n < 64; n++){
        float v = fmaf(wa, sx[n*3+0], fmaf(wb, sx[n*3+1], fmaf(wc, sx[n*3+2], bb)));
        g_h1[(size_t)(n0+n)*256 + t] = __float2half_rn(gelu_exact(v));
    }
}

// ---------------------------------------------------------------------------
// fp16 mma.sync GEMM: C[M x Ntot] = epi(A[M x K] @ W[Ntot x K]^T + bias)
// Block 128x128, BK=32, 256 threads = 8 warps (4m x 2n), warp tile 32x64.
// 4-stage cp.async, 64KB smem, 2 CTAs/SM.
// EPI: 0=fp32 store(+bias), 4=plain fp16.
// ---------------------------------------------------------------------------
#define GEMM_SMEM (64*1024)

template<int K, int EPI, bool HAS_BIAS>
__global__ __launch_bounds__(256, 2)
void gemm16(const __half* __restrict__ A, int lda,
            const __half* __restrict__ W, int ldw,
            const float* __restrict__ bias,
            void* __restrict__ Cout, int ldc)
{
    extern __shared__ char smem[];
    const int t    = threadIdx.x;
    const int lane = t & 31;
    const int w    = t >> 5;
    const int wm   = w >> 1, wn = w & 1;          // 4 x 2 warp grid
    const int gid  = lane >> 2, tig = lane & 3;
    const int m0   = blockIdx.x * 128;
    const int n0   = blockIdx.y * 128;
    const uint32_t sb = smem_u32(smem);

    // per-lane ldmatrix base offsets (k-slice s=0 baked in; s=1 -> XOR 0x20)
    uint32_t offA[2], offB[4];
    {
        const int l8 = lane & 7;
        const int h3 = (lane >> 3) & 1;
        const int h4 = lane >> 4;
        #pragma unroll
        for (int mi = 0; mi < 2; mi++){
            int rA = wm*32 + mi*16 + h3*8 + l8;
            int sw = (rA >> 1) & 3;
            offA[mi] = (uint32_t)(rA*64) + (uint32_t)((h4 ^ sw) << 4);
        }
        #pragma unroll
        for (int p = 0; p < 4; p++){
            int rB = wn*64 + p*16 + h4*8 + l8;
            int sw = (rB >> 1) & 3;
            offB[p] = (uint32_t)(rB*64) + (uint32_t)((h3 ^ sw) << 4);
        }
    }

    float acc[2][8][4];
    #pragma unroll
    for (int i = 0; i < 2; i++)
        #pragma unroll
        for (int j = 0; j < 8; j++)
            #pragma unroll
            for (int r = 0; r < 4; r++) acc[i][j][r] = 0.f;

    constexpr int NC = K / 32;

    auto produce = [&](int kc){
        const int st = kc & 3;
        #pragma unroll
        for (int it = 0; it < 2; it++){
            const int idx = it*256 + t, r = idx >> 2, c = idx & 3;
            uint32_t dst = sb + st*8192 + r*64 + (uint32_t)((c ^ ((r>>1)&3)) << 4);
            CP16(dst, (const void*)(A + (size_t)(m0 + r)*lda + kc*32 + c*8));
        }
        #pragma unroll
        for (int it = 0; it < 2; it++){
            const int idx = it*256 + t, rr = idx >> 2, cc = idx & 3;
            uint32_t db = sb + 32768 + st*8192 + rr*64 + (uint32_t)((cc ^ ((rr>>1)&3)) << 4);
            CP16(db, (const void*)(W + (size_t)(n0 + rr)*ldw + kc*32 + cc*8));
        }
        CP_COMMIT();
    };

    produce(0); produce(1); produce(2);

    #pragma unroll 1
    for (int kc = 0; kc < NC; kc++){
        CP_WAIT2();
        __syncthreads();
        const uint32_t aB = sb + (kc & 3)*8192;
        const uint32_t bB = sb + 32768u + (kc & 3)*8192;
        #pragma unroll
        for (int s = 0; s < 2; s++){
            const uint32_t sx = (uint32_t)s << 5;
            uint32_t afr[2][4], bfr[8][2];
            #pragma unroll
            for (int mi = 0; mi < 2; mi++)
                ldsm4(afr[mi][0], afr[mi][1], afr[mi][2], afr[mi][3],
                      aB + (offA[mi] ^ sx));
            #pragma unroll
            for (int p = 0; p < 4; p++)
                ldsm4(bfr[2*p][0], bfr[2*p][1], bfr[2*p+1][0], bfr[2*p+1][1],
                      bB + (offB[p] ^ sx));
            #pragma unroll
            for (int mi = 0; mi < 2; mi++)
                #pragma unroll
                for (int nj = 0; nj < 8; nj++)
                    mma16(acc[mi][nj], afr[mi], bfr[nj]);
        }
        if (kc + 3 < NC) produce(kc + 3); else CP_COMMIT();
    }

    // ---- epilogue ----
    #pragma unroll
    for (int mi = 0; mi < 2; mi++){
        const int r0 = m0 + wm*32 + mi*16 + gid;
        const int r1 = r0 + 8;
        #pragma unroll
        for (int nj = 0; nj < 8; nj++){
            const int cb = n0 + wn*64 + nj*8 + 2*tig;
            float v0 = acc[mi][nj][0], v1 = acc[mi][nj][1];
            float v2 = acc[mi][nj][2], v3 = acc[mi][nj][3];
            if (HAS_BIAS){
                const float b0 = bias[cb], b1 = bias[cb+1];
                v0 += b0; v1 += b1; v2 += b0; v3 += b1;
            }
            if (EPI == 0){
                float* C = (float*)Cout;
                *(float2*)(C + (size_t)r0*ldc + cb) = make_float2(v0, v1);
                *(float2*)(C + (size_t)r1*ldc + cb) = make_float2(v2, v3);
            } else {
                __half* C = (__half*)Cout;
                *(__half2*)(C + (size_t)r0*ldc + cb) = __floats2half2_rn(v0, v1);
                *(__half2*)(C + (size_t)r1*ldc + cb) = __floats2half2_rn(v2, v3);
            }
        }
    }
}

// ---------------------------------------------------------------------------
// Fused node-encoder kernel, 2 CTAs/SM: per block of 64 nodes:
//   phase 1: h2 = gelu(h1 @ W2^T + b2)            (K=256)  -> SMEM
//   phase 2: hh = h2 @ W3^T + b3 + fourier(pos)   (K=256)  -> gmem fp16
// SMEM 64KB: ph1: W2 3x16KB at [0,48K), A(h1) 3x4KB at [48K,60K);
//            ph2: h2 64x512B at [0,32K), W3 2x16KB at [32K,64K).
// ---------------------------------------------------------------------------
#define FUSED_SMEM (64*1024)

__global__ __launch_bounds__(256, 2)
void node_fused(const __half* __restrict__ h1g,
                const __half* __restrict__ W2, const float* __restrict__ b2,
                const __half* __restrict__ W3, const float* __restrict__ b3,
                const float* __restrict__ pos, const float* __restrict__ bfour,
                __half* __restrict__ hh)
{
    extern __shared__ char smem[];
    const int t    = threadIdx.x;
    const int lane = t & 31;
    const int w    = t >> 5;
    const int wm   = w >> 2, wn = w & 3;          // 2 x 4 warp grid
    const int gid  = lane >> 2, tig = lane & 3;
    const int m0   = blockIdx.x * 64;
    const uint32_t sb = smem_u32(smem);

    // per-lane ldmatrix offsets
    uint32_t offA[2], offB[4], baseM[2];
    int swM[2];
    const int l8 = lane & 7;
    const int h3 = (lane >> 3) & 1;
    const int h4 = lane >> 4;
    #pragma unroll
    for (int mi = 0; mi < 2; mi++){
        int rA = wm*32 + mi*16 + h3*8 + l8;          // 0..63
        int sw = (rA >> 1) & 3;
        offA[mi] = (uint32_t)(rA*64) + (uint32_t)((h4 ^ sw) << 4);
        baseM[mi] = (uint32_t)(rA*512);
        swM[mi] = rA & 7;
    }
    #pragma unroll
    for (int p = 0; p < 4; p++){
        int rB = wn*64 + p*16 + h4*8 + l8;           // 0..255
        int sw = (rB >> 1) & 3;
        offB[p] = (uint32_t)(rB*64) + (uint32_t)((h3 ^ sw) << 4);
    }

    float acc[2][8][4];
    #pragma unroll
    for (int i = 0; i < 2; i++)
        #pragma unroll
        for (int j = 0; j < 8; j++)
            #pragma unroll
            for (int r = 0; r < 4; r++) acc[i][j][r] = 0.f;

    // ---- phase 1 producer: A = h1 rows (cp.async), B = W2 (cp.async)
    auto produce1 = [&](int kc, int st){
        const int r = t >> 2, c = t & 3;             // r: 0..63
        uint32_t da = sb + 49152 + st*4096 + r*64 + (uint32_t)((c ^ ((r>>1)&3)) << 4);
        CP16(da, (const void*)(h1g + (size_t)(m0 + r)*256 + kc*32 + c*8));
        #pragma unroll
        for (int it = 0; it < 4; it++){
            const int idx = it*256 + t, rr = idx >> 2, cc = idx & 3;
            uint32_t db = sb + st*16384 + rr*64 + (uint32_t)((cc ^ ((rr>>1)&3)) << 4);
            CP16(db, (const void*)(W2 + (size_t)rr*256 + kc*32 + cc*8));
        }
        CP_COMMIT();
    };

    produce1(0, 0); produce1(1, 1);

    int ccur = 0, pcur = 2;
    #pragma unroll 1
    for (int kc = 0; kc < 8; kc++){
        CP_WAIT1();
        __syncthreads();
        const uint32_t aB = sb + 49152u + ccur*4096;
        const uint32_t bB = sb + ccur*16384;
        #pragma unroll
        for (int s = 0; s < 2; s++){
            const uint32_t sx = (uint32_t)s << 5;
            uint32_t afr[2][4], bfr[8][2];
            #pragma unroll
            for (int mi = 0; mi < 2; mi++)
                ldsm4(afr[mi][0], afr[mi][1], afr[mi][2], afr[mi][3],
                      aB + (offA[mi] ^ sx));
            #pragma unroll
            for (int p = 0; p < 4; p++)
                ldsm4(bfr[2*p][0], bfr[2*p][1], bfr[2*p+1][0], bfr[2*p+1][1],
                      bB + (offB[p] ^ sx));
            #pragma unroll
            for (int mi = 0; mi < 2; mi++)
                #pragma unroll
                for (int nj = 0; nj < 8; nj++)
                    mma16(acc[mi][nj], afr[mi], bfr[nj]);
        }
        if (kc + 2 < 8) produce1(kc + 2, pcur); else CP_COMMIT();
        ccur = (ccur == 2) ? 0 : ccur + 1;
        pcur = (pcur == 2) ? 0 : pcur + 1;
    }

    __syncthreads();   // everyone done reading phase-1 tiles

    // ---- phase 2 W3 producer into [32K,64K), 2 stages
    auto produce2 = [&](int kc){
        const int st = kc & 1;
        #pragma unroll
        for (int it = 0; it < 4; it++){
            const int idx = it*256 + t, rr = idx >> 2, cc = idx & 3;
            uint32_t db = sb + 32768 + st*16384 + rr*64 + (uint32_t)((cc ^ ((rr>>1)&3)) << 4);
            CP16(db, (const void*)(W3 + (size_t)rr*256 + kc*32 + cc*8));
        }
        CP_COMMIT();
    };
    produce2(0);

    // ---- epilogue-1: h2 = gelu(acc + b2) -> fp16 SMEM at [0, 32K)
    #pragma unroll
    for (int mi = 0; mi < 2; mi++){
        const int lr0 = wm*32 + mi*16 + gid;
        const int lr1 = lr0 + 8;
        #pragma unroll
        for (int nj = 0; nj < 8; nj++){
            const int cb = wn*64 + nj*8 + 2*tig;
            const float b0 = b2[cb], b1 = b2[cb+1];
            __half2 lo = __floats2half2_rn(gelu_exact(acc[mi][nj][0] + b0),
                                           gelu_exact(acc[mi][nj][1] + b1));
            __half2 hi = __floats2half2_rn(gelu_exact(acc[mi][nj][2] + b0),
                                           gelu_exact(acc[mi][nj][3] + b1));
            const int blk = cb >> 3;
            *(__half2*)(smem + lr0*512 + ((blk ^ (lr0 & 7)) << 4) + 4*tig) = lo;
            *(__half2*)(smem + lr1*512 + ((blk ^ (lr1 & 7)) << 4) + 4*tig) = hi;
            acc[mi][nj][0] = 0.f; acc[mi][nj][1] = 0.f;
            acc[mi][nj][2] = 0.f; acc[mi][nj][3] = 0.f;
        }
    }

    // ---- phase 2 main loop (K=256, 8 chunks)
    #pragma unroll 1
    for (int kc = 0; kc < 8; kc++){
        __syncthreads();                 // prev compute done; h2 visible (kc=0)
        if (kc + 1 < 8) produce2(kc + 1); else CP_COMMIT();
        CP_WAIT1();
        __syncthreads();
        const uint32_t bB = sb + 32768u + (kc & 1)*16384;
        #pragma unroll
        for (int s = 0; s < 2; s++){
            const uint32_t sx = (uint32_t)s << 5;
            uint32_t afr[2][4], bfr[8][2];
            #pragma unroll
            for (int mi = 0; mi < 2; mi++){
                const int blk = kc*4 + h4;
                const uint32_t offM = (uint32_t)((blk ^ swM[mi]) << 4);
                ldsm4(afr[mi][0], afr[mi][1], afr[mi][2], afr[mi][3],
                      sb + baseM[mi] + (offM ^ sx));
            }
            #pragma unroll
            for (int p = 0; p < 4; p++)
                ldsm4(bfr[2*p][0], bfr[2*p][1], bfr[2*p+1][0], bfr[2*p+1][1],
                      bB + (offB[p] ^ sx));
            #pragma unroll
            for (int mi = 0; mi < 2; mi++)
                #pragma unroll
                for (int nj = 0; nj < 8; nj++)
                    mma16(acc[mi][nj], afr[mi], bfr[nj]);
        }
    }

    // ---- final epilogue: hh = acc + b3 + fourier -> fp16 gmem
    #pragma unroll
    for (int mi = 0; mi < 2; mi++){
        const int r0 = m0 + wm*32 + mi*16 + gid;
        const int r1 = r0 + 8;
        const float p00 = pos[(size_t)r0*2], p01 = pos[(size_t)r0*2 + 1];
        const float p10 = pos[(size_t)r1*2], p11 = pos[(size_t)r1*2 + 1];
        #pragma unroll
        for (int nj = 0; nj < 8; nj++){
            const int cb = wn*64 + nj*8 + 2*tig;
            const float b0 = b3[cb], b1 = b3[cb+1];
            float v0 = acc[mi][nj][0] + b0, v1 = acc[mi][nj][1] + b1;
            float v2 = acc[mi][nj][2] + b0, v3 = acc[mi][nj][3] + b1;
            const int o0 = cb, o1 = cb + 1;
            const float ba0 = bfour[(o0 & 127)*2], bb0 = bfour[(o0 & 127)*2 + 1];
            const float ba1 = bfour[(o1 & 127)*2], bb1 = bfour[(o1 & 127)*2 + 1];
            const float TP = 6.283185307179586f;
            float pl0 = TP*(p00*ba0 + p01*bb0), pl1 = TP*(p00*ba1 + p01*bb1);
            float ph0 = TP*(p10*ba0 + p11*bb0), ph1 = TP*(p10*ba1 + p11*bb1);
            v0 += (o0 < 128) ? __cosf(pl0) : __sinf(pl0);
            v1 += (o1 < 128) ? __cosf(pl1) : __sinf(pl1);
            v2 += (o0 < 128) ? __cosf(ph0) : __sinf(ph0);
            v3 += (o1 < 128) ? __cosf(ph1) : __sinf(ph1);
            *(__half2*)(hh + (size_t)r0*256 + cb) = __floats2half2_rn(v0, v1);
            *(__half2*)(hh + (size_t)r1*256 + cb) = __floats2half2_rn(v2, v3);
        }
    }
}

// ---------------------------------------------------------------------------
// Edge kernel (single phase now), 2 CTAs/SM: per block of 64 edges (= 4 dsts):
//   m2 = gelu([gelu(ea[src]+eb[dst])] @ W2^T + b2)   (K=512)
//   m2mean[dst] = mean_16(m2)  -> gmem fp16          (W3 hoisted out: linear)
// SMEM 64KB: W2 3x16KB at [0,48K), A 3x4KB at [48K,60K).
// ---------------------------------------------------------------------------
#define EDGE_SMEM (64*1024)

__global__ __launch_bounds__(256, 2)
void edge_fused(const __half* __restrict__ eaH, const float* __restrict__ ebF,
                const __half* __restrict__ W2, const float* __restrict__ b2,
                __half* __restrict__ m2mean, const int* __restrict__ me32)
{
    extern __shared__ char smem[];
    __shared__ int sSrc[64], sDst[64];
    const int t    = threadIdx.x;
    const int lane = t & 31;
    const int w    = t >> 5;
    const int wm   = w >> 2, wn = w & 3;          // 2 x 4 warp grid
    const int tig  = lane & 3;
    const int m0   = blockIdx.x * 64;
    const uint32_t sb = smem_u32(smem);

    if (t < 64){
        const int e = m0 + t; int s, d;
        if (g_is64){ d = me32[4*e]; s = me32[4*e+2]; }
        else       { d = me32[2*e]; s = me32[2*e+1]; }
        sSrc[t] = s; sDst[t] = d;
    }
    __syncthreads();

    // per-lane ldmatrix offsets
    uint32_t offA[2], offB[4];
    const int l8 = lane & 7;
    const int h3 = (lane >> 3) & 1;
    const int h4 = lane >> 4;
    #pragma unroll
    for (int mi = 0; mi < 2; mi++){
        int rA = wm*32 + mi*16 + h3*8 + l8;          // 0..63
        int sw = (rA >> 1) & 3;
        offA[mi] = (uint32_t)(rA*64) + (uint32_t)((h4 ^ sw) << 4);
    }
    #pragma unroll
    for (int p = 0; p < 4; p++){
        int rB = wn*64 + p*16 + h4*8 + l8;           // 0..255
        int sw = (rB >> 1) & 3;
        offB[p] = (uint32_t)(rB*64) + (uint32_t)((h3 ^ sw) << 4);
    }

    float acc[2][8][4];
    #pragma unroll
    for (int i = 0; i < 2; i++)
        #pragma unroll
        for (int j = 0; j < 8; j++)
            #pragma unroll
            for (int r = 0; r < 4; r++) acc[i][j][r] = 0.f;

    // ---- producer: A = gelu(ea[src]+eb[dst]) (STS), B = W2 (cp.async)
    auto produce1 = [&](int kc, int st){
        const int r = t >> 2, c = t & 3;             // r: 0..63
        const int k0 = kc*32 + c*8;
        uint4 av = *(const uint4*)(eaH + (size_t)sSrc[r]*512 + k0);
        const float* pb = ebF + (size_t)sDst[r]*512 + k0;
        float4 e0 = *(const float4*)pb, e1 = *(const float4*)(pb + 4);
        const __half2* ah = (const __half2*)&av;
        float2 f0 = __half22float2(ah[0]), f1 = __half22float2(ah[1]);
        float2 f2 = __half22float2(ah[2]), f3 = __half22float2(ah[3]);
        __half2 h0 = __floats2half2_rn(gelu_exact(f0.x+e0.x), gelu_exact(f0.y+e0.y));
        __half2 h1 = __floats2half2_rn(gelu_exact(f1.x+e0.z), gelu_exact(f1.y+e0.w));
        __half2 h2 = __floats2half2_rn(gelu_exact(f2.x+e1.x), gelu_exact(f2.y+e1.y));
        __half2 h3v = __floats2half2_rn(gelu_exact(f3.x+e1.z), gelu_exact(f3.y+e1.w));
        uint4 pk;
        pk.x = *reinterpret_cast<uint32_t*>(&h0);
        pk.y = *reinterpret_cast<uint32_t*>(&h1);
        pk.z = *reinterpret_cast<uint32_t*>(&h2);
        pk.w = *reinterpret_cast<uint32_t*>(&h3v);
        *(uint4*)(smem + 49152 + st*4096 + r*64 + ((c ^ ((r>>1)&3)) << 4)) = pk;
        #pragma unroll
        for (int it = 0; it < 4; it++){
            const int idx = it*256 + t, rr = idx >> 2, cc = idx & 3;
            uint32_t db = sb + st*16384 + rr*64 + (uint32_t)((cc ^ ((rr>>1)&3)) << 4);
            CP16(db, (const void*)(W2 + (size_t)rr*512 + kc*32 + cc*8));
        }
        CP_COMMIT();
    };

    produce1(0, 0); produce1(1, 1);

    int ccur = 0, pcur = 2;
    #pragma unroll 1
    for (int kc = 0; kc < 16; kc++){
        CP_WAIT1();
        __syncthreads();
        const uint32_t aB = sb + 49152u + ccur*4096;
        const uint32_t bB = sb + ccur*16384;
        #pragma unroll
        for (int s = 0; s < 2; s++){
            const uint32_t sx = (uint32_t)s << 5;
            uint32_t afr[2][4], bfr[8][2];
            #pragma unroll
            for (int mi = 0; mi < 2; mi++)
                ldsm4(afr[mi][0], afr[mi][1], afr[mi][2], afr[mi][3],
                      aB + (offA[mi] ^ sx));
            #pragma unroll
            for (int p = 0; p < 4; p++)
                ldsm4(bfr[2*p][0], bfr[2*p][1], bfr[2*p+1][0], bfr[2*p+1][1],
                      bB + (offB[p] ^ sx));
            #pragma unroll
            for (int mi = 0; mi < 2; mi++)
                #pragma unroll
                for (int nj = 0; nj < 8; nj++)
                    mma16(acc[mi][nj], afr[mi], bfr[nj]);
        }
        if (kc + 2 < 16) produce1(kc + 2, pcur); else CP_COMMIT();
        ccur = (ccur == 2) ? 0 : ccur + 1;
        pcur = (pcur == 2) ? 0 : pcur + 1;
    }

    // ---- epilogue: m2mean[dst] = mean_16( gelu(acc + b2) )
    // mi tile = 16 consecutive edges = exactly one dst (wm*2 + mi).
    #pragma unroll
    for (int mi = 0; mi < 2; mi++){
        #pragma unroll
        for (int nj = 0; nj < 8; nj++){
            const int cb = wn*64 + nj*8 + 2*tig;
            const float b0 = b2[cb], b1 = b2[cb+1];
            float s0 = gelu_exact(acc[mi][nj][0] + b0) + gelu_exact(acc[mi][nj][2] + b0);
            float s1 = gelu_exact(acc[mi][nj][1] + b1) + gelu_exact(acc[mi][nj][3] + b1);
            s0 += __shfl_xor_sync(0xffffffffu, s0, 4);
            s0 += __shfl_xor_sync(0xffffffffu, s0, 8);
            s0 += __shfl_xor_sync(0xffffffffu, s0, 16);
            s1 += __shfl_xor_sync(0xffffffffu, s1, 4);
            s1 += __shfl_xor_sync(0xffffffffu, s1, 8);
            s1 += __shfl_xor_sync(0xffffffffu, s1, 16);
            if (lane < 4){
                const int dst = (m0 >> 4) + wm*2 + mi;
                *(__half2*)(m2mean + (size_t)dst*256 + cb) =
                    __floats2half2_rn(s0 * 0.0625f, s1 * 0.0625f);
            }
        }
    }
}

// ---------------------------------------------------------------------------
extern "C" void kernel_launch(void* const* d_in, const int* in_sizes, int n_in,
                              void* d_out, int out_size)
{
    const float* x        = (const float*)d_in[0];
    const float* mesh_pos = (const float*)d_in[1];
    const int*   me32     = (const int*)  d_in[2];
    const float* ip_w1 = (const float*)d_in[4];
    const float* ip_b1 = (const float*)d_in[5];
    const float* ip_w2 = (const float*)d_in[6];
    const float* ip_b2 = (const float*)d_in[7];
    const float* ip_w3 = (const float*)d_in[8];
    const float* ip_b3 = (const float*)d_in[9];
    const float* bf    = (const float*)d_in[10];
    const float* mw1   = (const float*)d_in[11];
    const float* mb1   = (const float*)d_in[12];
    const float* mw2   = (const float*)d_in[13];
    const float* mb2   = (const float*)d_in[14];
    const float* mw3   = (const float*)d_in[15];
    const float* mb3   = (const float*)d_in[16];
    float* out = (float*)d_out;

    __half *h1p, *hhp, *eaHp, *w2h, *w3h, *mw1h, *mw2h, *mw3h;
    float  *ebp;
    cudaGetSymbolAddress((void**)&h1p,  g_h1);
    cudaGetSymbolAddress((void**)&hhp,  g_hh);
    cudaGetSymbolAddress((void**)&eaHp, g_eaH);
    cudaGetSymbolAddress((void**)&ebp,  g_eb);
    cudaGetSymbolAddress((void**)&w2h,  g_w2h);
    cudaGetSymbolAddress((void**)&w3h,  g_w3h);
    cudaGetSymbolAddress((void**)&mw1h, g_mw1h);
    cudaGetSymbolAddress((void**)&mw2h, g_mw2h);
    cudaGetSymbolAddress((void**)&mw3h, g_mw3h);

    cudaFuncSetAttribute(gemm16<256,4,false>, cudaFuncAttributeMaxDynamicSharedMemorySize, GEMM_SMEM);
    cudaFuncSetAttribute(gemm16<256,0,true >, cudaFuncAttributeMaxDynamicSharedMemorySize, GEMM_SMEM);
    cudaFuncSetAttribute(node_fused,          cudaFuncAttributeMaxDynamicSharedMemorySize, FUSED_SMEM);
    cudaFuncSetAttribute(edge_fused,          cudaFuncAttributeMaxDynamicSharedMemorySize, EDGE_SMEM);

    detect_kernel<<<1, 32>>>(me32);

    // single fp16 weight prep launch
    f2h_all<<<576, 256>>>(ip_w2, ip_w3, mw1, mw2, mw3, w2h, w3h, mw1h, mw2h, mw3h);

    // node encoder: h1, then fused layers 2+3 (+fourier) -> hh
    h1_kernel<<<N_NODES/64, 256>>>(x, ip_w1, ip_b1);
    node_fused<<<N_NODES/64, 256, FUSED_SMEM>>>(
        h1p, w2h, ip_b2, w3h, ip_b3, mesh_pos, bf, hhp);

    // hoisted edge layer-1 halves: ea fp16 (no bias), eb fp32 (+b1)
    gemm16<256,4,false><<<dim3(N_NODES/128,4), 256, GEMM_SMEM>>>(
        hhp, 256, mw1h, 512, nullptr, eaHp, 512);
    gemm16<256,0,true ><<<dim3(N_DST/128,4), 256, GEMM_SMEM>>>(
        hhp, 256, mw1h + 256, 512, mb1, ebp, 512);

    // edge layer 2 + segment mean (W3 hoisted past the mean)
    // m2mean reuses g_h1 (h1 is dead after node_fused)
    edge_fused<<<N_EDGES/64, 256, EDGE_SMEM>>>(
        eaHp, ebp, mw2h, mb2, h1p, me32);

    // final: out = m2mean @ W3^T + b3   (16384 x 256, K=256)
    gemm16<256,0,true ><<<dim3(N_DST/128,2), 256, GEMM_SMEM>>>(
        h1p, 256, mw3h, 256, mb3, out, 256);
}